// round 11
// baseline (speedup 1.0000x reference)
#include <cuda_runtime.h>
#include <cuda_fp16.h>
#include <cstdint>

#define NN 50000
#define EE 800000
#define F  128
#define WPAD 132            // transposed-weight row stride (floats): conflict-free
#define SCAN_BLK 1024
#define SCAN_TILES ((NN + SCAN_BLK - 1) / SCAN_BLK)   // 49

// ================= scratch =================
__device__ int    g_cnt[NN];
__device__ int    g_fill[NN];
__device__ int    g_incl[NN];            // per-tile inclusive scan
__device__ int    g_tsum[SCAN_TILES];    // tile totals
__device__ int    g_toff[SCAN_TILES];    // tile exclusive offsets
__device__ int    g_rowptr[NN + 1];
__device__ int    g_csrc[EE];
__device__ float  g_cew[EE];
__device__ float  g_neigh[(size_t)NN * F];
__device__ float  g_h1[(size_t)NN * F];
__device__ float  g_h2[(size_t)NN * F];
__device__ __half g_hh[(size_t)NN * F];  // half-precision gather operand

// ================= CSR build =================
__global__ void k_zero() {
    int i = blockIdx.x * blockDim.x + threadIdx.x;
    if (i < NN) { g_cnt[i] = 0; g_fill[i] = 0; }
}
__global__ void k_hist(const int* __restrict__ dst) {
    int e = blockIdx.x * blockDim.x + threadIdx.x;
    if (e < EE) atomicAdd(&g_cnt[dst[e]], 1);
}

// phase 1: per-tile inclusive scan (1024 threads, 1 elem/thread)
__global__ void k_scan1() {
    __shared__ int wsum[32];
    const int tid = threadIdx.x, lane = tid & 31, wid = tid >> 5;
    int idx = blockIdx.x * SCAN_BLK + tid;
    int x = (idx < NN) ? g_cnt[idx] : 0;
#pragma unroll
    for (int off = 1; off < 32; off <<= 1) {
        int y = __shfl_up_sync(0xffffffffu, x, off);
        if (lane >= off) x += y;
    }
    if (lane == 31) wsum[wid] = x;
    __syncthreads();
    if (wid == 0) {
        int s = wsum[lane];
#pragma unroll
        for (int off = 1; off < 32; off <<= 1) {
            int y = __shfl_up_sync(0xffffffffu, s, off);
            if (lane >= off) s += y;
        }
        wsum[lane] = s;
    }
    __syncthreads();
    int incl = x + (wid ? wsum[wid - 1] : 0);
    if (idx < NN) g_incl[idx] = incl;
    if (tid == SCAN_BLK - 1) g_tsum[blockIdx.x] = incl;
}
// phase 2: exclusive scan over tile sums (single tiny block)
__global__ void k_scan2() {
    __shared__ int sh[SCAN_TILES];
    const int tid = threadIdx.x;          // 64 threads
    if (tid < SCAN_TILES) sh[tid] = g_tsum[tid];
    __syncthreads();
    if (tid == 0) {
        int run = 0;
        for (int i = 0; i < SCAN_TILES; i++) { int v = sh[i]; sh[i] = run; run += v; }
        g_rowptr[NN] = run;
    }
    __syncthreads();
    if (tid < SCAN_TILES) g_toff[tid] = sh[tid];
}
// phase 3: rowptr[i] = toff[tile] + incl[i] - cnt[i]
__global__ void k_scan3() {
    int i = blockIdx.x * blockDim.x + threadIdx.x;
    if (i < NN) g_rowptr[i] = g_toff[i / SCAN_BLK] + g_incl[i] - g_cnt[i];
}

__global__ void k_scatter(const int* __restrict__ src, const int* __restrict__ dst,
                          const float* __restrict__ ew) {
    int e = blockIdx.x * blockDim.x + threadIdx.x;
    if (e < EE) {
        int d = dst[e];
        int p = g_rowptr[d] + atomicAdd(&g_fill[d], 1);
        g_csrc[p] = src[e];
        g_cew[p]  = ew[e];
    }
}

// ================= fp32 -> fp16 convert (layer-1 gather operand) =================
__global__ void k_cvt(const float* __restrict__ in) {
    int i = blockIdx.x * blockDim.x + threadIdx.x;      // NN*F/8 tasks of 8 floats
    if (i >= NN * F / 8) return;
    const float4 a = reinterpret_cast<const float4*>(in)[2 * i + 0];
    const float4 b = reinterpret_cast<const float4*>(in)[2 * i + 1];
    __half2 h0 = __floats2half2_rn(a.x, a.y);
    __half2 h1 = __floats2half2_rn(a.z, a.w);
    __half2 h2 = __floats2half2_rn(b.x, b.y);
    __half2 h3 = __floats2half2_rn(b.z, b.w);
    uint4 o;
    o.x = *reinterpret_cast<uint32_t*>(&h0);
    o.y = *reinterpret_cast<uint32_t*>(&h1);
    o.z = *reinterpret_cast<uint32_t*>(&h2);
    o.w = *reinterpret_cast<uint32_t*>(&h3);
    reinterpret_cast<uint4*>(g_hh)[i] = o;
}

// ================= aggregation: gather fp16 h, fp32 accumulate =================
__device__ __forceinline__ float4 ld_h4(int node, int lane) {
    const uint2 hv = *reinterpret_cast<const uint2*>(g_hh + (size_t)node * F + lane * 4);
    float2 p0 = __half22float2(*reinterpret_cast<const __half2*>(&hv.x));
    float2 p1 = __half22float2(*reinterpret_cast<const __half2*>(&hv.y));
    return make_float4(p0.x, p0.y, p1.x, p1.y);
}

__global__ void k_agg() {
    int v    = (blockIdx.x * blockDim.x + threadIdx.x) >> 5;
    int lane = threadIdx.x & 31;
    if (v >= NN) return;
    int s0 = g_rowptr[v], s1 = g_rowptr[v + 1];
    float4 a0 = make_float4(0.f, 0.f, 0.f, 0.f);
    float4 a1 = make_float4(0.f, 0.f, 0.f, 0.f);
    int e = s0;
    for (; e + 3 < s1; e += 4) {
        int   sa = g_csrc[e],     sb = g_csrc[e + 1];
        int   sc = g_csrc[e + 2], sd = g_csrc[e + 3];
        float wa = g_cew[e],      wb = g_cew[e + 1];
        float wc = g_cew[e + 2],  wd = g_cew[e + 3];
        float4 A = ld_h4(sa, lane);
        float4 B = ld_h4(sb, lane);
        float4 C = ld_h4(sc, lane);
        float4 D = ld_h4(sd, lane);
        a0.x += wa * A.x + wb * B.x;  a1.x += wc * C.x + wd * D.x;
        a0.y += wa * A.y + wb * B.y;  a1.y += wc * C.y + wd * D.y;
        a0.z += wa * A.z + wb * B.z;  a1.z += wc * C.z + wd * D.z;
        a0.w += wa * A.w + wb * B.w;  a1.w += wc * C.w + wd * D.w;
    }
    for (; e < s1; e++) {
        int   s  = g_csrc[e];
        float wt = g_cew[e];
        float4 A = ld_h4(s, lane);
        a0.x += wt * A.x; a0.y += wt * A.y;
        a0.z += wt * A.z; a0.w += wt * A.w;
    }
    int deg = s1 - s0;
    float invd = 1.0f / (float)(deg > 1 ? deg : 1);
    float4 o;
    o.x = (a0.x + a1.x) * invd;
    o.y = (a0.y + a1.y) * invd;
    o.z = (a0.z + a1.z) * invd;
    o.w = (a0.w + a1.w) * invd;
    *reinterpret_cast<float4*>(g_neigh + (size_t)v * F + lane * 4) = o;
}

// ================= packed-f32x2 helpers =================
__device__ __forceinline__ void fma2(unsigned long long& d,
                                     unsigned long long a, unsigned long long b) {
    asm("fma.rn.f32x2 %0, %1, %2, %3;" : "=l"(d) : "l"(a), "l"(b), "l"(d));
}
__device__ __forceinline__ float2 unpack2(unsigned long long v) {
    float2 f;
    asm("mov.b64 {%0, %1}, %2;" : "=f"(f.x), "=f"(f.y) : "l"(v));
    return f;
}

// ================= fused SAGE GEMM (R6 core) =================
template <bool HN, bool DOT, bool WH>
__global__ void __launch_bounds__(256, 2)
k_sage(const float* __restrict__ hin, const float* __restrict__ ws,
       const float* __restrict__ wn, const float* __restrict__ b,
       float* __restrict__ hout,
       const float* __restrict__ w2, const float* __restrict__ b2,
       float* __restrict__ outv) {
    extern __shared__ float sm[];
    float* s_w = sm;                 // [128][WPAD] transposed (reused per pass)
    float* s_t = sm + F * WPAD;      // [64][128] node tile

    const int tid  = threadIdx.x;
    const int lane = tid & 31;
    const int wid  = tid >> 5;
    const int nodeBase = blockIdx.x * 64;
    const int n0 = 8 * wid;

    unsigned long long acc2[8][4];
#pragma unroll
    for (int i = 0; i < 8; i++)
#pragma unroll
        for (int m = 0; m < 4; m++) acc2[i][m] = 0ull;

    const float* s_trow[8];
#pragma unroll
    for (int i = 0; i < 8; i++) s_trow[i] = s_t + (n0 + i) * F;
    const float* s_wrow[4];
#pragma unroll
    for (int m = 0; m < 4; m++) s_wrow[m] = s_w + (lane + 32 * m) * WPAD;

    for (int pass = 0; pass < (HN ? 2 : 1); pass++) {
        const float* W    = (pass == 0) ? ws : wn;
        const float* srcp = (pass == 0) ? hin : g_neigh;
        if (pass) __syncthreads();

        for (int task = wid; task < 128; task += 8) {
            int m  = task & 3;
            int k0 = (task >> 2) * 4;
            int j  = m * 32 + lane;
            float4 v;
            v.x = W[(k0 + 0) * F + j];
            v.y = W[(k0 + 1) * F + j];
            v.z = W[(k0 + 2) * F + j];
            v.w = W[(k0 + 3) * F + j];
            *reinterpret_cast<float4*>(s_w + j * WPAD + k0) = v;   // conflict-free
        }
        for (int t = tid; t < 64 * 32; t += 256) {
            int n = t >> 5, q = (t & 31) * 4;
            int v = nodeBase + n;
            float4 hv = make_float4(0.f, 0.f, 0.f, 0.f);
            if (v < NN) hv = *reinterpret_cast<const float4*>(srcp + (size_t)v * F + q);
            *reinterpret_cast<float4*>(s_t + n * F + q) = hv;
        }
        __syncthreads();

#pragma unroll 2
        for (int c = 0; c < 32; c++) {
            ulonglong2 w[4];
#pragma unroll
            for (int m = 0; m < 4; m++)
                w[m] = *reinterpret_cast<const ulonglong2*>(s_wrow[m] + c * 4);
#pragma unroll
            for (int i = 0; i < 8; i++) {
                ulonglong2 h = *reinterpret_cast<const ulonglong2*>(s_trow[i] + c * 4);
#pragma unroll
                for (int m = 0; m < 4; m++) {
                    fma2(acc2[i][m], h.x, w[m].x);
                    fma2(acc2[i][m], h.y, w[m].y);
                }
            }
        }
    }

    float bj[4];
#pragma unroll
    for (int m = 0; m < 4; m++) bj[m] = b[lane + 32 * m];

    if (!DOT) {
#pragma unroll
        for (int i = 0; i < 8; i++) {
            int v = nodeBase + n0 + i;
            if (v < NN) {
#pragma unroll
                for (int m = 0; m < 4; m++) {
                    float2 f = unpack2(acc2[i][m]);
                    float  r = fmaxf(f.x + f.y + bj[m], 0.f);
                    hout[(size_t)v * F + lane + 32 * m] = r;
                    if (WH) g_hh[(size_t)v * F + lane + 32 * m] = __float2half(r);
                }
            }
        }
    } else {
        float w2j[4];
#pragma unroll
        for (int m = 0; m < 4; m++) w2j[m] = w2[lane + 32 * m];
        float bias2 = b2[0];
#pragma unroll
        for (int i = 0; i < 8; i++) {
            float s = 0.f;
#pragma unroll
            for (int m = 0; m < 4; m++) {
                float2 f = unpack2(acc2[i][m]);
                s += fmaxf(f.x + f.y + bj[m], 0.f) * w2j[m];
            }
#pragma unroll
            for (int o = 16; o; o >>= 1) s += __shfl_xor_sync(0xffffffffu, s, o);
            int v = nodeBase + n0 + i;
            if (lane == 0 && v < NN) outv[v] = s + bias2;
        }
    }
}

// ================= launch =================
extern "C" void kernel_launch(void* const* d_in, const int* in_sizes, int n_in,
                              void* d_out, int out_size) {
    const float* inputs = (const float*)d_in[0];
    const float* ew     = (const float*)d_in[1];
    const int*   src    = (const int*)d_in[2];
    const int*   dst    = (const int*)d_in[3];
    const float* ws1 = (const float*)d_in[4];
    const float* wn1 = (const float*)d_in[5];
    const float* b1  = (const float*)d_in[6];
    const float* ws2 = (const float*)d_in[7];
    const float* wn2 = (const float*)d_in[8];
    const float* b2  = (const float*)d_in[9];
    const float* ws3 = (const float*)d_in[10];
    const float* wn3 = (const float*)d_in[11];
    const float* b3  = (const float*)d_in[12];
    const float* wl1 = (const float*)d_in[13];
    const float* bl1 = (const float*)d_in[14];
    const float* wl2 = (const float*)d_in[15];
    const float* bl2 = (const float*)d_in[16];
    float* out = (float*)d_out;

    float *h1, *h2;
    cudaGetSymbolAddress((void**)&h1, g_h1);
    cudaGetSymbolAddress((void**)&h2, g_h2);

    const size_t smem = (size_t)(F * WPAD + 64 * F) * sizeof(float); // 100352 B
    cudaFuncSetAttribute((const void*)k_sage<true,  false, true>,  cudaFuncAttributeMaxDynamicSharedMemorySize, (int)smem);
    cudaFuncSetAttribute((const void*)k_sage<true,  false, false>, cudaFuncAttributeMaxDynamicSharedMemorySize, (int)smem);
    cudaFuncSetAttribute((const void*)k_sage<false, true,  false>, cudaFuncAttributeMaxDynamicSharedMemorySize, (int)smem);

    const int TB = 256;
    const int aggBlocks  = (NN * 32 + TB - 1) / TB;   // warp per node
    const int sageBlocks = (NN + 63) / 64;            // 782

    // convert layer-1 gather operand + CSR build (parallel 3-phase scan)
    k_cvt    <<<(NN * F / 8 + TB - 1) / TB, TB>>>(inputs);
    k_zero   <<<(NN + TB - 1) / TB, TB>>>();
    k_hist   <<<(EE + TB - 1) / TB, TB>>>(dst);
    k_scan1  <<<SCAN_TILES, SCAN_BLK>>>();
    k_scan2  <<<1, 64>>>();
    k_scan3  <<<(NN + TB - 1) / TB, TB>>>();
    k_scatter<<<(EE + TB - 1) / TB, TB>>>(src, dst, ew);

    // layer 1: gather(fp16 inputs) -> sage (writes h1 fp32 + g_hh fp16)
    k_agg<<<aggBlocks, TB>>>();
    k_sage<true, false, true><<<sageBlocks, 256, smem>>>(inputs, ws1, wn1, b1, h1,
                                                         nullptr, nullptr, nullptr);
    // layer 2
    k_agg<<<aggBlocks, TB>>>();
    k_sage<true, false, true><<<sageBlocks, 256, smem>>>(h1, ws2, wn2, b2, h2,
                                                         nullptr, nullptr, nullptr);
    // layer 3 (no fp16 copy needed)
    k_agg<<<aggBlocks, TB>>>();
    k_sage<true, false, false><<<sageBlocks, 256, smem>>>(h2, ws3, wn3, b3, h1,
                                                          nullptr, nullptr, nullptr);
    // lin1 + lin2 fused
    k_sage<false, true, false><<<sageBlocks, 256, smem>>>(h1, wl1, nullptr, bl1, nullptr,
                                                          wl2, bl2, out);
}

// round 12
// speedup vs baseline: 1.0726x; 1.0726x over previous
#include <cuda_runtime.h>
#include <cuda_fp16.h>
#include <cstdint>

#define NN 50000
#define EE 800000
#define F  128
#define WPAD 132            // transposed-weight row stride (floats): conflict-free
#define SCAN_BLK 1024
#define SCAN_TILES ((NN + SCAN_BLK - 1) / SCAN_BLK)   // 49

// ================= scratch =================
__device__ int    g_cnt[NN];
__device__ int    g_fill[NN];
__device__ int    g_incl[NN];
__device__ int    g_tsum[SCAN_TILES];
__device__ int    g_toff[SCAN_TILES];
__device__ int    g_rowptr[NN + 1];
__device__ int    g_csrc[EE];
__device__ float  g_cew[EE];
__device__ float  g_neigh[(size_t)NN * F];
__device__ float  g_h1[(size_t)NN * F];
__device__ float  g_h2[(size_t)NN * F];
__device__ __half g_hh[(size_t)NN * F];  // half-precision gather operand

// ================= CSR build =================
__global__ void k_zero() {
    int i = blockIdx.x * blockDim.x + threadIdx.x;
    if (i < NN) { g_cnt[i] = 0; g_fill[i] = 0; }
}
__global__ void k_hist(const int* __restrict__ dst) {
    int e = blockIdx.x * blockDim.x + threadIdx.x;
    if (e < EE) atomicAdd(&g_cnt[dst[e]], 1);
}
__global__ void k_scan1() {
    __shared__ int wsum[32];
    const int tid = threadIdx.x, lane = tid & 31, wid = tid >> 5;
    int idx = blockIdx.x * SCAN_BLK + tid;
    int x = (idx < NN) ? g_cnt[idx] : 0;
#pragma unroll
    for (int off = 1; off < 32; off <<= 1) {
        int y = __shfl_up_sync(0xffffffffu, x, off);
        if (lane >= off) x += y;
    }
    if (lane == 31) wsum[wid] = x;
    __syncthreads();
    if (wid == 0) {
        int s = wsum[lane];
#pragma unroll
        for (int off = 1; off < 32; off <<= 1) {
            int y = __shfl_up_sync(0xffffffffu, s, off);
            if (lane >= off) s += y;
        }
        wsum[lane] = s;
    }
    __syncthreads();
    int incl = x + (wid ? wsum[wid - 1] : 0);
    if (idx < NN) g_incl[idx] = incl;
    if (tid == SCAN_BLK - 1) g_tsum[blockIdx.x] = incl;
}
__global__ void k_scan2() {
    __shared__ int sh[SCAN_TILES];
    const int tid = threadIdx.x;
    if (tid < SCAN_TILES) sh[tid] = g_tsum[tid];
    __syncthreads();
    if (tid == 0) {
        int run = 0;
        for (int i = 0; i < SCAN_TILES; i++) { int v = sh[i]; sh[i] = run; run += v; }
        g_rowptr[NN] = run;
    }
    __syncthreads();
    if (tid < SCAN_TILES) g_toff[tid] = sh[tid];
}
__global__ void k_scan3() {
    int i = blockIdx.x * blockDim.x + threadIdx.x;
    if (i < NN) g_rowptr[i] = g_toff[i / SCAN_BLK] + g_incl[i] - g_cnt[i];
}
__global__ void k_scatter(const int* __restrict__ src, const int* __restrict__ dst,
                          const float* __restrict__ ew) {
    int e = blockIdx.x * blockDim.x + threadIdx.x;
    if (e < EE) {
        int d = dst[e];
        int p = g_rowptr[d] + atomicAdd(&g_fill[d], 1);
        g_csrc[p] = src[e];
        g_cew[p]  = ew[e];
    }
}

// ================= fp32 -> fp16 convert =================
__global__ void k_cvt(const float* __restrict__ in) {
    int i = blockIdx.x * blockDim.x + threadIdx.x;
    if (i >= NN * F / 8) return;
    const float4 a = reinterpret_cast<const float4*>(in)[2 * i + 0];
    const float4 b = reinterpret_cast<const float4*>(in)[2 * i + 1];
    __half2 h0 = __floats2half2_rn(a.x, a.y);
    __half2 h1 = __floats2half2_rn(a.z, a.w);
    __half2 h2 = __floats2half2_rn(b.x, b.y);
    __half2 h3 = __floats2half2_rn(b.z, b.w);
    uint4 o;
    o.x = *reinterpret_cast<uint32_t*>(&h0);
    o.y = *reinterpret_cast<uint32_t*>(&h1);
    o.z = *reinterpret_cast<uint32_t*>(&h2);
    o.w = *reinterpret_cast<uint32_t*>(&h3);
    reinterpret_cast<uint4*>(g_hh)[i] = o;
}

// ================= aggregation: warp/node, 2 edges across lane halves =================
// lane = half*16 + fl : half in {0,1} picks edge parity, fl picks 8-feature group.
// Each lane loads 16 B (8 halves) per edge -> full 128-feature row covered by 16
// lanes; unroll x2 puts 4 edges in flight per warp iteration. Final shfl_xor(16)
// combines the two halves' partial sums.
__device__ __forceinline__ void acc_edge(float acc[8], int node, int fl, float wt) {
    const uint4 hv = *reinterpret_cast<const uint4*>(g_hh + (size_t)node * F + fl * 8);
    const __half2* hp = reinterpret_cast<const __half2*>(&hv);
#pragma unroll
    for (int q = 0; q < 4; q++) {
        float2 p = __half22float2(hp[q]);
        acc[2 * q + 0] += wt * p.x;
        acc[2 * q + 1] += wt * p.y;
    }
}

__global__ void k_agg() {
    int v    = (blockIdx.x * blockDim.x + threadIdx.x) >> 5;
    int lane = threadIdx.x & 31;
    if (v >= NN) return;
    const int half = lane >> 4;     // 0 or 1
    const int fl   = lane & 15;     // feature group (8 floats)

    int s0 = g_rowptr[v], s1 = g_rowptr[v + 1];
    int deg = s1 - s0;

    float acc[8];
#pragma unroll
    for (int q = 0; q < 8; q++) acc[q] = 0.f;

    // this half processes edges s0+half, s0+half+2, ... ; unroll 2 -> stride 4
    int e = s0 + half;
    for (; e + 2 < s1; e += 4) {
        int   sa = g_csrc[e],  sb = g_csrc[e + 2];
        float wa = g_cew[e],   wb = g_cew[e + 2];
        acc_edge(acc, sa, fl, wa);
        acc_edge(acc, sb, fl, wb);
    }
    if (e < s1) acc_edge(acc, g_csrc[e], fl, g_cew[e]);

    // combine halves: lane l and l^16 hold same feature slots, different edges
#pragma unroll
    for (int q = 0; q < 8; q++)
        acc[q] += __shfl_xor_sync(0xffffffffu, acc[q], 16);

    float invd = 1.0f / (float)(deg > 1 ? deg : 1);
    if (half == 0) {
        float4 o0, o1;
        o0.x = acc[0] * invd; o0.y = acc[1] * invd;
        o0.z = acc[2] * invd; o0.w = acc[3] * invd;
        o1.x = acc[4] * invd; o1.y = acc[5] * invd;
        o1.z = acc[6] * invd; o1.w = acc[7] * invd;
        float* dstp = g_neigh + (size_t)v * F + fl * 8;
        *reinterpret_cast<float4*>(dstp)     = o0;
        *reinterpret_cast<float4*>(dstp + 4) = o1;
    }
}

// ================= packed-f32x2 helpers =================
__device__ __forceinline__ void fma2(unsigned long long& d,
                                     unsigned long long a, unsigned long long b) {
    asm("fma.rn.f32x2 %0, %1, %2, %3;" : "=l"(d) : "l"(a), "l"(b), "l"(d));
}
__device__ __forceinline__ float2 unpack2(unsigned long long v) {
    float2 f;
    asm("mov.b64 {%0, %1}, %2;" : "=f"(f.x), "=f"(f.y) : "l"(v));
    return f;
}

// ================= fused SAGE GEMM (R6 core) =================
template <bool HN, bool DOT, bool WH>
__global__ void __launch_bounds__(256, 2)
k_sage(const float* __restrict__ hin, const float* __restrict__ ws,
       const float* __restrict__ wn, const float* __restrict__ b,
       float* __restrict__ hout,
       const float* __restrict__ w2, const float* __restrict__ b2,
       float* __restrict__ outv) {
    extern __shared__ float sm[];
    float* s_w = sm;                 // [128][WPAD] transposed (reused per pass)
    float* s_t = sm + F * WPAD;      // [64][128] node tile

    const int tid  = threadIdx.x;
    const int lane = tid & 31;
    const int wid  = tid >> 5;
    const int nodeBase = blockIdx.x * 64;
    const int n0 = 8 * wid;

    unsigned long long acc2[8][4];
#pragma unroll
    for (int i = 0; i < 8; i++)
#pragma unroll
        for (int m = 0; m < 4; m++) acc2[i][m] = 0ull;

    const float* s_trow[8];
#pragma unroll
    for (int i = 0; i < 8; i++) s_trow[i] = s_t + (n0 + i) * F;
    const float* s_wrow[4];
#pragma unroll
    for (int m = 0; m < 4; m++) s_wrow[m] = s_w + (lane + 32 * m) * WPAD;

    for (int pass = 0; pass < (HN ? 2 : 1); pass++) {
        const float* W    = (pass == 0) ? ws : wn;
        const float* srcp = (pass == 0) ? hin : g_neigh;
        if (pass) __syncthreads();

        for (int task = wid; task < 128; task += 8) {
            int m  = task & 3;
            int k0 = (task >> 2) * 4;
            int j  = m * 32 + lane;
            float4 v;
            v.x = W[(k0 + 0) * F + j];
            v.y = W[(k0 + 1) * F + j];
            v.z = W[(k0 + 2) * F + j];
            v.w = W[(k0 + 3) * F + j];
            *reinterpret_cast<float4*>(s_w + j * WPAD + k0) = v;   // conflict-free
        }
        for (int t = tid; t < 64 * 32; t += 256) {
            int n = t >> 5, q = (t & 31) * 4;
            int v = nodeBase + n;
            float4 hv = make_float4(0.f, 0.f, 0.f, 0.f);
            if (v < NN) hv = *reinterpret_cast<const float4*>(srcp + (size_t)v * F + q);
            *reinterpret_cast<float4*>(s_t + n * F + q) = hv;
        }
        __syncthreads();

#pragma unroll 2
        for (int c = 0; c < 32; c++) {
            ulonglong2 w[4];
#pragma unroll
            for (int m = 0; m < 4; m++)
                w[m] = *reinterpret_cast<const ulonglong2*>(s_wrow[m] + c * 4);
#pragma unroll
            for (int i = 0; i < 8; i++) {
                ulonglong2 h = *reinterpret_cast<const ulonglong2*>(s_trow[i] + c * 4);
#pragma unroll
                for (int m = 0; m < 4; m++) {
                    fma2(acc2[i][m], h.x, w[m].x);
                    fma2(acc2[i][m], h.y, w[m].y);
                }
            }
        }
    }

    float bj[4];
#pragma unroll
    for (int m = 0; m < 4; m++) bj[m] = b[lane + 32 * m];

    if (!DOT) {
#pragma unroll
        for (int i = 0; i < 8; i++) {
            int v = nodeBase + n0 + i;
            if (v < NN) {
#pragma unroll
                for (int m = 0; m < 4; m++) {
                    float2 f = unpack2(acc2[i][m]);
                    float  r = fmaxf(f.x + f.y + bj[m], 0.f);
                    hout[(size_t)v * F + lane + 32 * m] = r;
                    if (WH) g_hh[(size_t)v * F + lane + 32 * m] = __float2half(r);
                }
            }
        }
    } else {
        float w2j[4];
#pragma unroll
        for (int m = 0; m < 4; m++) w2j[m] = w2[lane + 32 * m];
        float bias2 = b2[0];
#pragma unroll
        for (int i = 0; i < 8; i++) {
            float s = 0.f;
#pragma unroll
            for (int m = 0; m < 4; m++) {
                float2 f = unpack2(acc2[i][m]);
                s += fmaxf(f.x + f.y + bj[m], 0.f) * w2j[m];
            }
#pragma unroll
            for (int o = 16; o; o >>= 1) s += __shfl_xor_sync(0xffffffffu, s, o);
            int v = nodeBase + n0 + i;
            if (lane == 0 && v < NN) outv[v] = s + bias2;
        }
    }
}

// ================= launch =================
extern "C" void kernel_launch(void* const* d_in, const int* in_sizes, int n_in,
                              void* d_out, int out_size) {
    const float* inputs = (const float*)d_in[0];
    const float* ew     = (const float*)d_in[1];
    const int*   src    = (const int*)d_in[2];
    const int*   dst    = (const int*)d_in[3];
    const float* ws1 = (const float*)d_in[4];
    const float* wn1 = (const float*)d_in[5];
    const float* b1  = (const float*)d_in[6];
    const float* ws2 = (const float*)d_in[7];
    const float* wn2 = (const float*)d_in[8];
    const float* b2  = (const float*)d_in[9];
    const float* ws3 = (const float*)d_in[10];
    const float* wn3 = (const float*)d_in[11];
    const float* b3  = (const float*)d_in[12];
    const float* wl1 = (const float*)d_in[13];
    const float* bl1 = (const float*)d_in[14];
    const float* wl2 = (const float*)d_in[15];
    const float* bl2 = (const float*)d_in[16];
    float* out = (float*)d_out;

    float *h1, *h2;
    cudaGetSymbolAddress((void**)&h1, g_h1);
    cudaGetSymbolAddress((void**)&h2, g_h2);

    const size_t smem = (size_t)(F * WPAD + 64 * F) * sizeof(float); // 100352 B
    cudaFuncSetAttribute((const void*)k_sage<true,  false, true>,  cudaFuncAttributeMaxDynamicSharedMemorySize, (int)smem);
    cudaFuncSetAttribute((const void*)k_sage<true,  false, false>, cudaFuncAttributeMaxDynamicSharedMemorySize, (int)smem);
    cudaFuncSetAttribute((const void*)k_sage<false, true,  false>, cudaFuncAttributeMaxDynamicSharedMemorySize, (int)smem);

    const int TB = 256;
    const int aggBlocks  = (NN * 32 + TB - 1) / TB;   // warp per node
    const int sageBlocks = (NN + 63) / 64;            // 782

    k_cvt    <<<(NN * F / 8 + TB - 1) / TB, TB>>>(inputs);
    k_zero   <<<(NN + TB - 1) / TB, TB>>>();
    k_hist   <<<(EE + TB - 1) / TB, TB>>>(dst);
    k_scan1  <<<SCAN_TILES, SCAN_BLK>>>();
    k_scan2  <<<1, 64>>>();
    k_scan3  <<<(NN + TB - 1) / TB, TB>>>();
    k_scatter<<<(EE + TB - 1) / TB, TB>>>(src, dst, ew);

    // layer 1
    k_agg<<<aggBlocks, TB>>>();
    k_sage<true, false, true><<<sageBlocks, 256, smem>>>(inputs, ws1, wn1, b1, h1,
                                                         nullptr, nullptr, nullptr);
    // layer 2
    k_agg<<<aggBlocks, TB>>>();
    k_sage<true, false, true><<<sageBlocks, 256, smem>>>(h1, ws2, wn2, b2, h2,
                                                         nullptr, nullptr, nullptr);
    // layer 3
    k_agg<<<aggBlocks, TB>>>();
    k_sage<true, false, false><<<sageBlocks, 256, smem>>>(h2, ws3, wn3, b3, h1,
                                                          nullptr, nullptr, nullptr);
    // lin1 + lin2 fused
    k_sage<false, true, false><<<sageBlocks, 256, smem>>>(h1, wl1, nullptr, bl1, nullptr,
                                                          wl2, bl2, out);
}

// round 13
// speedup vs baseline: 1.0772x; 1.0043x over previous
#include <cuda_runtime.h>
#include <cuda_fp16.h>
#include <cstdint>

#define NN 50000
#define EE 800000
#define F  128
#define WPAD 132            // transposed-weight row stride (floats): conflict-free
#define SCAN_BLK 1024
#define SCAN_TILES ((NN + SCAN_BLK - 1) / SCAN_BLK)   // 49

// ================= scratch =================
__device__ int    g_cnt[NN];
__device__ int    g_fill[NN];
__device__ int    g_incl[NN];
__device__ int    g_tsum[SCAN_TILES];
__device__ int    g_toff[SCAN_TILES];
__device__ int    g_rowptr[NN + 1];
__device__ int    g_csrc[EE];
__device__ float  g_cew[EE];
__device__ float  g_neigh[(size_t)NN * F];
__device__ float  g_h1[(size_t)NN * F];
__device__ float  g_h2[(size_t)NN * F];
__device__ __half g_hh[(size_t)NN * F];  // half-precision gather operand

// ================= CSR build =================
__global__ void k_zero() {
    int i = blockIdx.x * blockDim.x + threadIdx.x;
    if (i < NN) { g_cnt[i] = 0; g_fill[i] = 0; }
}
__global__ void k_hist(const int* __restrict__ dst) {
    int e = blockIdx.x * blockDim.x + threadIdx.x;
    if (e < EE) atomicAdd(&g_cnt[dst[e]], 1);
}
__global__ void k_scan1() {
    __shared__ int wsum[32];
    const int tid = threadIdx.x, lane = tid & 31, wid = tid >> 5;
    int idx = blockIdx.x * SCAN_BLK + tid;
    int x = (idx < NN) ? g_cnt[idx] : 0;
#pragma unroll
    for (int off = 1; off < 32; off <<= 1) {
        int y = __shfl_up_sync(0xffffffffu, x, off);
        if (lane >= off) x += y;
    }
    if (lane == 31) wsum[wid] = x;
    __syncthreads();
    if (wid == 0) {
        int s = wsum[lane];
#pragma unroll
        for (int off = 1; off < 32; off <<= 1) {
            int y = __shfl_up_sync(0xffffffffu, s, off);
            if (lane >= off) s += y;
        }
        wsum[lane] = s;
    }
    __syncthreads();
    int incl = x + (wid ? wsum[wid - 1] : 0);
    if (idx < NN) g_incl[idx] = incl;
    if (tid == SCAN_BLK - 1) g_tsum[blockIdx.x] = incl;
}
__global__ void k_scan2() {
    __shared__ int sh[SCAN_TILES];
    const int tid = threadIdx.x;
    if (tid < SCAN_TILES) sh[tid] = g_tsum[tid];
    __syncthreads();
    if (tid == 0) {
        int run = 0;
        for (int i = 0; i < SCAN_TILES; i++) { int v = sh[i]; sh[i] = run; run += v; }
        g_rowptr[NN] = run;
    }
    __syncthreads();
    if (tid < SCAN_TILES) g_toff[tid] = sh[tid];
}
__global__ void k_scan3() {
    int i = blockIdx.x * blockDim.x + threadIdx.x;
    if (i < NN) g_rowptr[i] = g_toff[i / SCAN_BLK] + g_incl[i] - g_cnt[i];
}
__global__ void k_scatter(const int* __restrict__ src, const int* __restrict__ dst,
                          const float* __restrict__ ew) {
    int e = blockIdx.x * blockDim.x + threadIdx.x;
    if (e < EE) {
        int d = dst[e];
        int p = g_rowptr[d] + atomicAdd(&g_fill[d], 1);
        g_csrc[p] = src[e];
        g_cew[p]  = ew[e];
    }
}

// ================= fp32 -> fp16 convert =================
__global__ void k_cvt(const float* __restrict__ in) {
    int i = blockIdx.x * blockDim.x + threadIdx.x;
    if (i >= NN * F / 8) return;
    const float4 a = reinterpret_cast<const float4*>(in)[2 * i + 0];
    const float4 b = reinterpret_cast<const float4*>(in)[2 * i + 1];
    __half2 h0 = __floats2half2_rn(a.x, a.y);
    __half2 h1 = __floats2half2_rn(a.z, a.w);
    __half2 h2 = __floats2half2_rn(b.x, b.y);
    __half2 h3 = __floats2half2_rn(b.z, b.w);
    uint4 o;
    o.x = *reinterpret_cast<uint32_t*>(&h0);
    o.y = *reinterpret_cast<uint32_t*>(&h1);
    o.z = *reinterpret_cast<uint32_t*>(&h2);
    o.w = *reinterpret_cast<uint32_t*>(&h3);
    reinterpret_cast<uint4*>(g_hh)[i] = o;
}

// ================= aggregation: warp/node, 2 lane-halves x unroll-4 =================
// lane = half*16 + fl. Each half processes edges s0+half, stride 2; unroll 4
// -> 8 edges in flight per warp. shfl_xor(16) combines halves at the end.
__device__ __forceinline__ void acc_edge(float acc[8], int node, int fl, float wt) {
    const uint4 hv = *reinterpret_cast<const uint4*>(g_hh + (size_t)node * F + fl * 8);
    const __half2* hp = reinterpret_cast<const __half2*>(&hv);
#pragma unroll
    for (int q = 0; q < 4; q++) {
        float2 p = __half22float2(hp[q]);
        acc[2 * q + 0] += wt * p.x;
        acc[2 * q + 1] += wt * p.y;
    }
}

__global__ void k_agg() {
    int v    = (blockIdx.x * blockDim.x + threadIdx.x) >> 5;
    int lane = threadIdx.x & 31;
    if (v >= NN) return;
    const int half = lane >> 4;     // 0 or 1
    const int fl   = lane & 15;     // feature group (8 floats)

    int s0 = g_rowptr[v], s1 = g_rowptr[v + 1];
    int deg = s1 - s0;

    float acc[8];
#pragma unroll
    for (int q = 0; q < 8; q++) acc[q] = 0.f;

    int e = s0 + half;
    // unroll 4: edges e, e+2, e+4, e+6 (this half), batched loads -> MLP ~8/warp
    for (; e + 6 < s1; e += 8) {
        int   sa = g_csrc[e],      sb = g_csrc[e + 2];
        int   sc = g_csrc[e + 4],  sd = g_csrc[e + 6];
        float wa = g_cew[e],       wb = g_cew[e + 2];
        float wc = g_cew[e + 4],   wd = g_cew[e + 6];
        acc_edge(acc, sa, fl, wa);
        acc_edge(acc, sb, fl, wb);
        acc_edge(acc, sc, fl, wc);
        acc_edge(acc, sd, fl, wd);
    }
    for (; e < s1; e += 2)
        acc_edge(acc, g_csrc[e], fl, g_cew[e]);

#pragma unroll
    for (int q = 0; q < 8; q++)
        acc[q] += __shfl_xor_sync(0xffffffffu, acc[q], 16);

    float invd = 1.0f / (float)(deg > 1 ? deg : 1);
    if (half == 0) {
        float4 o0, o1;
        o0.x = acc[0] * invd; o0.y = acc[1] * invd;
        o0.z = acc[2] * invd; o0.w = acc[3] * invd;
        o1.x = acc[4] * invd; o1.y = acc[5] * invd;
        o1.z = acc[6] * invd; o1.w = acc[7] * invd;
        float* dstp = g_neigh + (size_t)v * F + fl * 8;
        *reinterpret_cast<float4*>(dstp)     = o0;
        *reinterpret_cast<float4*>(dstp + 4) = o1;
    }
}

// ================= packed-f32x2 helpers =================
__device__ __forceinline__ void fma2(unsigned long long& d,
                                     unsigned long long a, unsigned long long b) {
    asm("fma.rn.f32x2 %0, %1, %2, %3;" : "=l"(d) : "l"(a), "l"(b), "l"(d));
}
__device__ __forceinline__ float2 unpack2(unsigned long long v) {
    float2 f;
    asm("mov.b64 {%0, %1}, %2;" : "=f"(f.x), "=f"(f.y) : "l"(v));
    return f;
}

// ================= fused SAGE GEMM (R6 core) =================
template <bool HN, bool DOT, bool WH>
__global__ void __launch_bounds__(256, 2)
k_sage(const float* __restrict__ hin, const float* __restrict__ ws,
       const float* __restrict__ wn, const float* __restrict__ b,
       float* __restrict__ hout,
       const float* __restrict__ w2, const float* __restrict__ b2,
       float* __restrict__ outv) {
    extern __shared__ float sm[];
    float* s_w = sm;                 // [128][WPAD] transposed (reused per pass)
    float* s_t = sm + F * WPAD;      // [64][128] node tile

    const int tid  = threadIdx.x;
    const int lane = tid & 31;
    const int wid  = tid >> 5;
    const int nodeBase = blockIdx.x * 64;
    const int n0 = 8 * wid;

    unsigned long long acc2[8][4];
#pragma unroll
    for (int i = 0; i < 8; i++)
#pragma unroll
        for (int m = 0; m < 4; m++) acc2[i][m] = 0ull;

    const float* s_trow[8];
#pragma unroll
    for (int i = 0; i < 8; i++) s_trow[i] = s_t + (n0 + i) * F;
    const float* s_wrow[4];
#pragma unroll
    for (int m = 0; m < 4; m++) s_wrow[m] = s_w + (lane + 32 * m) * WPAD;

    for (int pass = 0; pass < (HN ? 2 : 1); pass++) {
        const float* W    = (pass == 0) ? ws : wn;
        const float* srcp = (pass == 0) ? hin : g_neigh;
        if (pass) __syncthreads();

        for (int task = wid; task < 128; task += 8) {
            int m  = task & 3;
            int k0 = (task >> 2) * 4;
            int j  = m * 32 + lane;
            float4 v;
            v.x = W[(k0 + 0) * F + j];
            v.y = W[(k0 + 1) * F + j];
            v.z = W[(k0 + 2) * F + j];
            v.w = W[(k0 + 3) * F + j];
            *reinterpret_cast<float4*>(s_w + j * WPAD + k0) = v;   // conflict-free
        }
        for (int t = tid; t < 64 * 32; t += 256) {
            int n = t >> 5, q = (t & 31) * 4;
            int v = nodeBase + n;
            float4 hv = make_float4(0.f, 0.f, 0.f, 0.f);
            if (v < NN) hv = *reinterpret_cast<const float4*>(srcp + (size_t)v * F + q);
            *reinterpret_cast<float4*>(s_t + n * F + q) = hv;
        }
        __syncthreads();

#pragma unroll 2
        for (int c = 0; c < 32; c++) {
            ulonglong2 w[4];
#pragma unroll
            for (int m = 0; m < 4; m++)
                w[m] = *reinterpret_cast<const ulonglong2*>(s_wrow[m] + c * 4);
#pragma unroll
            for (int i = 0; i < 8; i++) {
                ulonglong2 h = *reinterpret_cast<const ulonglong2*>(s_trow[i] + c * 4);
#pragma unroll
                for (int m = 0; m < 4; m++) {
                    fma2(acc2[i][m], h.x, w[m].x);
                    fma2(acc2[i][m], h.y, w[m].y);
                }
            }
        }
    }

    float bj[4];
#pragma unroll
    for (int m = 0; m < 4; m++) bj[m] = b[lane + 32 * m];

    if (!DOT) {
#pragma unroll
        for (int i = 0; i < 8; i++) {
            int v = nodeBase + n0 + i;
            if (v < NN) {
#pragma unroll
                for (int m = 0; m < 4; m++) {
                    float2 f = unpack2(acc2[i][m]);
                    float  r = fmaxf(f.x + f.y + bj[m], 0.f);
                    hout[(size_t)v * F + lane + 32 * m] = r;
                    if (WH) g_hh[(size_t)v * F + lane + 32 * m] = __float2half(r);
                }
            }
        }
    } else {
        float w2j[4];
#pragma unroll
        for (int m = 0; m < 4; m++) w2j[m] = w2[lane + 32 * m];
        float bias2 = b2[0];
#pragma unroll
        for (int i = 0; i < 8; i++) {
            float s = 0.f;
#pragma unroll
            for (int m = 0; m < 4; m++) {
                float2 f = unpack2(acc2[i][m]);
                s += fmaxf(f.x + f.y + bj[m], 0.f) * w2j[m];
            }
#pragma unroll
            for (int o = 16; o; o >>= 1) s += __shfl_xor_sync(0xffffffffu, s, o);
            int v = nodeBase + n0 + i;
            if (lane == 0 && v < NN) outv[v] = s + bias2;
        }
    }
}

// ================= launch =================
extern "C" void kernel_launch(void* const* d_in, const int* in_sizes, int n_in,
                              void* d_out, int out_size) {
    const float* inputs = (const float*)d_in[0];
    const float* ew     = (const float*)d_in[1];
    const int*   src    = (const int*)d_in[2];
    const int*   dst    = (const int*)d_in[3];
    const float* ws1 = (const float*)d_in[4];
    const float* wn1 = (const float*)d_in[5];
    const float* b1  = (const float*)d_in[6];
    const float* ws2 = (const float*)d_in[7];
    const float* wn2 = (const float*)d_in[8];
    const float* b2  = (const float*)d_in[9];
    const float* ws3 = (const float*)d_in[10];
    const float* wn3 = (const float*)d_in[11];
    const float* b3  = (const float*)d_in[12];
    const float* wl1 = (const float*)d_in[13];
    const float* bl1 = (const float*)d_in[14];
    const float* wl2 = (const float*)d_in[15];
    const float* bl2 = (const float*)d_in[16];
    float* out = (float*)d_out;

    float *h1, *h2;
    cudaGetSymbolAddress((void**)&h1, g_h1);
    cudaGetSymbolAddress((void**)&h2, g_h2);

    const size_t smem = (size_t)(F * WPAD + 64 * F) * sizeof(float); // 100352 B
    cudaFuncSetAttribute((const void*)k_sage<true,  false, true>,  cudaFuncAttributeMaxDynamicSharedMemorySize, (int)smem);
    cudaFuncSetAttribute((const void*)k_sage<true,  false, false>, cudaFuncAttributeMaxDynamicSharedMemorySize, (int)smem);
    cudaFuncSetAttribute((const void*)k_sage<false, true,  false>, cudaFuncAttributeMaxDynamicSharedMemorySize, (int)smem);

    const int TB = 256;
    const int aggBlocks  = (NN * 32 + TB - 1) / TB;   // warp per node
    const int sageBlocks = (NN + 63) / 64;            // 782

    k_cvt    <<<(NN * F / 8 + TB - 1) / TB, TB>>>(inputs);
    k_zero   <<<(NN + TB - 1) / TB, TB>>>();
    k_hist   <<<(EE + TB - 1) / TB, TB>>>(dst);
    k_scan1  <<<SCAN_TILES, SCAN_BLK>>>();
    k_scan2  <<<1, 64>>>();
    k_scan3  <<<(NN + TB - 1) / TB, TB>>>();
    k_scatter<<<(EE + TB - 1) / TB, TB>>>(src, dst, ew);

    // layer 1
    k_agg<<<aggBlocks, TB>>>();
    k_sage<true, false, true><<<sageBlocks, 256, smem>>>(inputs, ws1, wn1, b1, h1,
                                                         nullptr, nullptr, nullptr);
    // layer 2
    k_agg<<<aggBlocks, TB>>>();
    k_sage<true, false, true><<<sageBlocks, 256, smem>>>(h1, ws2, wn2, b2, h2,
                                                         nullptr, nullptr, nullptr);
    // layer 3
    k_agg<<<aggBlocks, TB>>>();
    k_sage<true, false, false><<<sageBlocks, 256, smem>>>(h2, ws3, wn3, b3, h1,
                                                          nullptr, nullptr, nullptr);
    // lin1 + lin2 fused
    k_sage<false, true, false><<<sageBlocks, 256, smem>>>(h1, wl1, nullptr, bl1, nullptr,
                                                          wl2, bl2, out);
}

// round 14
// speedup vs baseline: 1.7313x; 1.6073x over previous
#include <cuda_runtime.h>
#include <cuda_fp16.h>
#include <cstdint>

#define NN 50000
#define EE 800000
#define F  128
#define SCAN_BLK 1024
#define SCAN_TILES ((NN + SCAN_BLK - 1) / SCAN_BLK)   // 49

// HMMA smem layout (halves, padded rows: 128+8 -> conflict-free ldmatrix)
#define HPAD 136
#define ROWB (HPAD * 2)                 // 272 B per row
#define OFF_WH 0
#define OFF_WL (128 * ROWB)             // 34816
#define OFF_AH (2 * 128 * ROWB)         // 69632
#define OFF_AL (2 * 128 * ROWB + 64 * ROWB)   // 87040
#define SMEM_BYTES (2 * 128 * ROWB + 2 * 64 * ROWB)  // 104448

// ================= scratch =================
__device__ int    g_cnt[NN];
__device__ int    g_fill[NN];
__device__ int    g_incl[NN];
__device__ int    g_tsum[SCAN_TILES];
__device__ int    g_toff[SCAN_TILES];
__device__ int    g_rowptr[NN + 1];
__device__ int    g_csrc[EE];
__device__ float  g_cew[EE];
__device__ float  g_neigh[(size_t)NN * F];
__device__ float  g_h1[(size_t)NN * F];
__device__ float  g_h2[(size_t)NN * F];
__device__ __half g_hh[(size_t)NN * F];  // half-precision gather operand

// ================= CSR build =================
__global__ void k_zero() {
    int i = blockIdx.x * blockDim.x + threadIdx.x;
    if (i < NN) { g_cnt[i] = 0; g_fill[i] = 0; }
}
__global__ void k_hist(const int* __restrict__ dst) {
    int e = blockIdx.x * blockDim.x + threadIdx.x;
    if (e < EE) atomicAdd(&g_cnt[dst[e]], 1);
}
__global__ void k_scan1() {
    __shared__ int wsum[32];
    const int tid = threadIdx.x, lane = tid & 31, wid = tid >> 5;
    int idx = blockIdx.x * SCAN_BLK + tid;
    int x = (idx < NN) ? g_cnt[idx] : 0;
#pragma unroll
    for (int off = 1; off < 32; off <<= 1) {
        int y = __shfl_up_sync(0xffffffffu, x, off);
        if (lane >= off) x += y;
    }
    if (lane == 31) wsum[wid] = x;
    __syncthreads();
    if (wid == 0) {
        int s = wsum[lane];
#pragma unroll
        for (int off = 1; off < 32; off <<= 1) {
            int y = __shfl_up_sync(0xffffffffu, s, off);
            if (lane >= off) s += y;
        }
        wsum[lane] = s;
    }
    __syncthreads();
    int incl = x + (wid ? wsum[wid - 1] : 0);
    if (idx < NN) g_incl[idx] = incl;
    if (tid == SCAN_BLK - 1) g_tsum[blockIdx.x] = incl;
}
__global__ void k_scan2() {
    __shared__ int sh[SCAN_TILES];
    const int tid = threadIdx.x;
    if (tid < SCAN_TILES) sh[tid] = g_tsum[tid];
    __syncthreads();
    if (tid == 0) {
        int run = 0;
        for (int i = 0; i < SCAN_TILES; i++) { int v = sh[i]; sh[i] = run; run += v; }
        g_rowptr[NN] = run;
    }
    __syncthreads();
    if (tid < SCAN_TILES) g_toff[tid] = sh[tid];
}
__global__ void k_scan3() {
    int i = blockIdx.x * blockDim.x + threadIdx.x;
    if (i < NN) g_rowptr[i] = g_toff[i / SCAN_BLK] + g_incl[i] - g_cnt[i];
}
__global__ void k_scatter(const int* __restrict__ src, const int* __restrict__ dst,
                          const float* __restrict__ ew) {
    int e = blockIdx.x * blockDim.x + threadIdx.x;
    if (e < EE) {
        int d = dst[e];
        int p = g_rowptr[d] + atomicAdd(&g_fill[d], 1);
        g_csrc[p] = src[e];
        g_cew[p]  = ew[e];
    }
}

// ================= fp32 -> fp16 convert =================
__global__ void k_cvt(const float* __restrict__ in) {
    int i = blockIdx.x * blockDim.x + threadIdx.x;
    if (i >= NN * F / 8) return;
    const float4 a = reinterpret_cast<const float4*>(in)[2 * i + 0];
    const float4 b = reinterpret_cast<const float4*>(in)[2 * i + 1];
    __half2 h0 = __floats2half2_rn(a.x, a.y);
    __half2 h1 = __floats2half2_rn(a.z, a.w);
    __half2 h2 = __floats2half2_rn(b.x, b.y);
    __half2 h3 = __floats2half2_rn(b.z, b.w);
    uint4 o;
    o.x = *reinterpret_cast<uint32_t*>(&h0);
    o.y = *reinterpret_cast<uint32_t*>(&h1);
    o.z = *reinterpret_cast<uint32_t*>(&h2);
    o.w = *reinterpret_cast<uint32_t*>(&h3);
    reinterpret_cast<uint4*>(g_hh)[i] = o;
}

// ================= aggregation (R13: warp/node, lane halves, unroll-4) =========
__device__ __forceinline__ void acc_edge(float acc[8], int node, int fl, float wt) {
    const uint4 hv = *reinterpret_cast<const uint4*>(g_hh + (size_t)node * F + fl * 8);
    const __half2* hp = reinterpret_cast<const __half2*>(&hv);
#pragma unroll
    for (int q = 0; q < 4; q++) {
        float2 p = __half22float2(hp[q]);
        acc[2 * q + 0] += wt * p.x;
        acc[2 * q + 1] += wt * p.y;
    }
}

__global__ void k_agg() {
    int v    = (blockIdx.x * blockDim.x + threadIdx.x) >> 5;
    int lane = threadIdx.x & 31;
    if (v >= NN) return;
    const int half = lane >> 4;
    const int fl   = lane & 15;

    int s0 = g_rowptr[v], s1 = g_rowptr[v + 1];
    int deg = s1 - s0;

    float acc[8];
#pragma unroll
    for (int q = 0; q < 8; q++) acc[q] = 0.f;

    int e = s0 + half;
    for (; e + 6 < s1; e += 8) {
        int   sa = g_csrc[e],      sb = g_csrc[e + 2];
        int   sc = g_csrc[e + 4],  sd = g_csrc[e + 6];
        float wa = g_cew[e],       wb = g_cew[e + 2];
        float wc = g_cew[e + 4],   wd = g_cew[e + 6];
        acc_edge(acc, sa, fl, wa);
        acc_edge(acc, sb, fl, wb);
        acc_edge(acc, sc, fl, wc);
        acc_edge(acc, sd, fl, wd);
    }
    for (; e < s1; e += 2)
        acc_edge(acc, g_csrc[e], fl, g_cew[e]);

#pragma unroll
    for (int q = 0; q < 8; q++)
        acc[q] += __shfl_xor_sync(0xffffffffu, acc[q], 16);

    float invd = 1.0f / (float)(deg > 1 ? deg : 1);
    if (half == 0) {
        float4 o0, o1;
        o0.x = acc[0] * invd; o0.y = acc[1] * invd;
        o0.z = acc[2] * invd; o0.w = acc[3] * invd;
        o1.x = acc[4] * invd; o1.y = acc[5] * invd;
        o1.z = acc[6] * invd; o1.w = acc[7] * invd;
        float* dstp = g_neigh + (size_t)v * F + fl * 8;
        *reinterpret_cast<float4*>(dstp)     = o0;
        *reinterpret_cast<float4*>(dstp + 4) = o1;
    }
}

// ================= HMMA helpers =================
__device__ __forceinline__ uint32_t cvta_sm(const void* p) {
    uint32_t a;
    asm("{ .reg .u64 t; cvta.to.shared.u64 t, %1; cvt.u32.u64 %0, t; }" : "=r"(a) : "l"(p));
    return a;
}
__device__ __forceinline__ void ldsm4(uint32_t* r, uint32_t addr) {
    asm volatile("ldmatrix.sync.aligned.m8n8.x4.shared.b16 {%0,%1,%2,%3}, [%4];"
        : "=r"(r[0]), "=r"(r[1]), "=r"(r[2]), "=r"(r[3]) : "r"(addr));
}
__device__ __forceinline__ void ldsm4t(uint32_t* r, uint32_t addr) {
    asm volatile("ldmatrix.sync.aligned.m8n8.x4.trans.shared.b16 {%0,%1,%2,%3}, [%4];"
        : "=r"(r[0]), "=r"(r[1]), "=r"(r[2]), "=r"(r[3]) : "r"(addr));
}
__device__ __forceinline__ void mma16816(float* d, const uint32_t* a, const uint32_t* b) {
    asm volatile("mma.sync.aligned.m16n8k16.row.col.f32.f16.f16.f32 "
        "{%0,%1,%2,%3}, {%4,%5,%6,%7}, {%8,%9}, {%0,%1,%2,%3};"
        : "+f"(d[0]), "+f"(d[1]), "+f"(d[2]), "+f"(d[3])
        : "r"(a[0]), "r"(a[1]), "r"(a[2]), "r"(a[3]), "r"(b[0]), "r"(b[1]));
}
__device__ __forceinline__ uint32_t pack2h(__half a, __half b) {
    __half2 h = __halves2half2(a, b);
    return *reinterpret_cast<uint32_t*>(&h);
}
// split float -> (hi, lo) fp16
__device__ __forceinline__ void split_h(float x, __half& h, __half& l) {
    h = __float2half_rn(x);
    l = __float2half_rn(x - __half2float(h));
}

// ================= fused SAGE GEMM via Markidis-split fp16 HMMA =================
// 256 threads / 8 warps; tile 64 nodes x 128 feats. Warp wm=wid&3 -> rows
// 16*wm..+15; wn2=wid>>2 -> cols 64*wn2..+63. 3-term split: ah*bh+ah*bl+al*bh.
template <bool HN, bool DOT, bool WH>
__global__ void __launch_bounds__(256, 2)
k_sage(const float* __restrict__ hin, const float* __restrict__ ws,
       const float* __restrict__ wn, const float* __restrict__ b,
       float* __restrict__ hout,
       const float* __restrict__ w2, const float* __restrict__ b2,
       float* __restrict__ outv) {
    extern __shared__ char smc[];
    const uint32_t sbase = cvta_sm(smc);

    const int tid  = threadIdx.x;
    const int lane = tid & 31;
    const int wid  = tid >> 5;
    const int wm   = wid & 3;
    const int wn2  = wid >> 2;
    const int nodeBase = blockIdx.x * 64;

    float d[8][4];
#pragma unroll
    for (int nf = 0; nf < 8; nf++)
#pragma unroll
        for (int q = 0; q < 4; q++) d[nf][q] = 0.f;

    const int lr = lane & 15, lh = lane >> 4;
    const uint32_t aH = sbase + OFF_AH + (16 * wm + lr) * ROWB + lh * 16;
    const uint32_t aL = sbase + OFF_AL + (16 * wm + lr) * ROWB + lh * 16;
    const uint32_t bH = sbase + OFF_WH + lr * ROWB + (wn2 * 64 + lh * 8) * 2;
    const uint32_t bL = sbase + OFF_WL + lr * ROWB + (wn2 * 64 + lh * 8) * 2;

    for (int pass = 0; pass < (HN ? 2 : 1); pass++) {
        const float* W    = (pass == 0) ? ws : wn;
        const float* srcp = (pass == 0) ? hin : g_neigh;
        if (pass) __syncthreads();

        // ---- stage weights (hi/lo split), [k][n] row-major ----
        for (int t = tid; t < 128 * 32; t += 256) {
            int k = t >> 5, q = (t & 31) * 4;
            float4 w = *reinterpret_cast<const float4*>(W + k * F + q);
            __half h0, h1, h2, h3, l0, l1, l2, l3;
            split_h(w.x, h0, l0); split_h(w.y, h1, l1);
            split_h(w.z, h2, l2); split_h(w.w, h3, l3);
            uint2 ph = make_uint2(pack2h(h0, h1), pack2h(h2, h3));
            uint2 pl = make_uint2(pack2h(l0, l1), pack2h(l2, l3));
            *reinterpret_cast<uint2*>(smc + OFF_WH + k * ROWB + q * 2) = ph;
            *reinterpret_cast<uint2*>(smc + OFF_WL + k * ROWB + q * 2) = pl;
        }
        // ---- stage node tile (hi/lo split) ----
        for (int t = tid; t < 64 * 32; t += 256) {
            int n = t >> 5, q = (t & 31) * 4;
            int v = nodeBase + n;
            float4 hv = make_float4(0.f, 0.f, 0.f, 0.f);
            if (v < NN) hv = *reinterpret_cast<const float4*>(srcp + (size_t)v * F + q);
            __half h0, h1, h2, h3, l0, l1, l2, l3;
            split_h(hv.x, h0, l0); split_h(hv.y, h1, l1);
            split_h(hv.z, h2, l2); split_h(hv.w, h3, l3);
            uint2 ph = make_uint2(pack2h(h0, h1), pack2h(h2, h3));
            uint2 pl = make_uint2(pack2h(l0, l1), pack2h(l2, l3));
            *reinterpret_cast<uint2*>(smc + OFF_AH + n * ROWB + q * 2) = ph;
            *reinterpret_cast<uint2*>(smc + OFF_AL + n * ROWB + q * 2) = pl;
        }
        __syncthreads();

        // ---- mma mainloop: 8 k-tiles of 16 ----
#pragma unroll
        for (int kt = 0; kt < 8; kt++) {
            uint32_t ah[4], al[4];
            ldsm4(ah, aH + kt * 32);
            ldsm4(al, aL + kt * 32);
            uint32_t bh[16], bl[16];
#pragma unroll
            for (int g = 0; g < 4; g++) {
                ldsm4t(bh + 4 * g, bH + kt * (16 * ROWB) + g * 32);
                ldsm4t(bl + 4 * g, bL + kt * (16 * ROWB) + g * 32);
            }
#pragma unroll
            for (int nf = 0; nf < 8; nf++) {
                mma16816(d[nf], ah, bh + 2 * nf);
                mma16816(d[nf], ah, bl + 2 * nf);
                mma16816(d[nf], al, bh + 2 * nf);
            }
        }
    }

    // ---- epilogue ----
    const int r0 = lane >> 2;           // 0..7
    const int c0 = (lane & 3) * 2;
    const int vA = nodeBase + 16 * wm + r0;
    const int vB = vA + 8;

    if (!DOT) {
#pragma unroll
        for (int nf = 0; nf < 8; nf++) {
            int col = wn2 * 64 + nf * 8 + c0;
            float2 bb = *reinterpret_cast<const float2*>(b + col);
            float o0 = fmaxf(d[nf][0] + bb.x, 0.f);
            float o1 = fmaxf(d[nf][1] + bb.y, 0.f);
            float o2 = fmaxf(d[nf][2] + bb.x, 0.f);
            float o3 = fmaxf(d[nf][3] + bb.y, 0.f);
            if (vA < NN) {
                *reinterpret_cast<float2*>(hout + (size_t)vA * F + col) = make_float2(o0, o1);
                if (WH) *reinterpret_cast<__half2*>(g_hh + (size_t)vA * F + col) = __floats2half2_rn(o0, o1);
            }
            if (vB < NN) {
                *reinterpret_cast<float2*>(hout + (size_t)vB * F + col) = make_float2(o2, o3);
                if (WH) *reinterpret_cast<__half2*>(g_hh + (size_t)vB * F + col) = __floats2half2_rn(o2, o3);
            }
        }
    } else {
        __syncthreads();                      // done reading smem; reuse for reduce
        float* s_red = reinterpret_cast<float*>(smc);
        if (tid < 64) s_red[tid] = 0.f;
        __syncthreads();
        float pl = 0.f, ph = 0.f;
#pragma unroll
        for (int nf = 0; nf < 8; nf++) {
            int col = wn2 * 64 + nf * 8 + c0;
            float2 bb = *reinterpret_cast<const float2*>(b + col);
            float2 ww = *reinterpret_cast<const float2*>(w2 + col);
            pl += fmaxf(d[nf][0] + bb.x, 0.f) * ww.x + fmaxf(d[nf][1] + bb.y, 0.f) * ww.y;
            ph += fmaxf(d[nf][2] + bb.x, 0.f) * ww.x + fmaxf(d[nf][3] + bb.y, 0.f) * ww.y;
        }
        pl += __shfl_xor_sync(0xffffffffu, pl, 1);
        pl += __shfl_xor_sync(0xffffffffu, pl, 2);
        ph += __shfl_xor_sync(0xffffffffu, ph, 1);
        ph += __shfl_xor_sync(0xffffffffu, ph, 2);
        if ((lane & 3) == 0) {
            atomicAdd(&s_red[16 * wm + r0],     pl);
            atomicAdd(&s_red[16 * wm + r0 + 8], ph);
        }
        __syncthreads();
        if (tid < 64) {
            int v = nodeBase + tid;
            if (v < NN) outv[v] = s_red[tid] + b2[0];
        }
    }
}

// ================= launch =================
extern "C" void kernel_launch(void* const* d_in, const int* in_sizes, int n_in,
                              void* d_out, int out_size) {
    const float* inputs = (const float*)d_in[0];
    const float* ew     = (const float*)d_in[1];
    const int*   src    = (const int*)d_in[2];
    const int*   dst    = (const int*)d_in[3];
    const float* ws1 = (const float*)d_in[4];
    const float* wn1 = (const float*)d_in[5];
    const float* b1  = (const float*)d_in[6];
    const float* ws2 = (const float*)d_in[7];
    const float* wn2 = (const float*)d_in[8];
    const float* b2  = (const float*)d_in[9];
    const float* ws3 = (const float*)d_in[10];
    const float* wn3 = (const float*)d_in[11];
    const float* b3  = (const float*)d_in[12];
    const float* wl1 = (const float*)d_in[13];
    const float* bl1 = (const float*)d_in[14];
    const float* wl2 = (const float*)d_in[15];
    const float* bl2 = (const float*)d_in[16];
    float* out = (float*)d_out;

    float *h1, *h2;
    cudaGetSymbolAddress((void**)&h1, g_h1);
    cudaGetSymbolAddress((void**)&h2, g_h2);

    cudaFuncSetAttribute((const void*)k_sage<true,  false, true>,  cudaFuncAttributeMaxDynamicSharedMemorySize, SMEM_BYTES);
    cudaFuncSetAttribute((const void*)k_sage<true,  false, false>, cudaFuncAttributeMaxDynamicSharedMemorySize, SMEM_BYTES);
    cudaFuncSetAttribute((const void*)k_sage<false, true,  false>, cudaFuncAttributeMaxDynamicSharedMemorySize, SMEM_BYTES);

    const int TB = 256;
    const int aggBlocks  = (NN * 32 + TB - 1) / TB;   // warp per node
    const int sageBlocks = (NN + 63) / 64;            // 782

    k_cvt    <<<(NN * F / 8 + TB - 1) / TB, TB>>>(inputs);
    k_zero   <<<(NN + TB - 1) / TB, TB>>>();
    k_hist   <<<(EE + TB - 1) / TB, TB>>>(dst);
    k_scan1  <<<SCAN_TILES, SCAN_BLK>>>();
    k_scan2  <<<1, 64>>>();
    k_scan3  <<<(NN + TB - 1) / TB, TB>>>();
    k_scatter<<<(EE + TB - 1) / TB, TB>>>(src, dst, ew);

    // layer 1
    k_agg<<<aggBlocks, TB>>>();
    k_sage<true, false, true><<<sageBlocks, 256, SMEM_BYTES>>>(inputs, ws1, wn1, b1, h1,
                                                               nullptr, nullptr, nullptr);
    // layer 2
    k_agg<<<aggBlocks, TB>>>();
    k_sage<true, false, true><<<sageBlocks, 256, SMEM_BYTES>>>(h1, ws2, wn2, b2, h2,
                                                               nullptr, nullptr, nullptr);
    // layer 3
    k_agg<<<aggBlocks, TB>>>();
    k_sage<true, false, false><<<sageBlocks, 256, SMEM_BYTES>>>(h2, ws3, wn3, b3, h1,
                                                                nullptr, nullptr, nullptr);
    // lin1 + lin2 fused
    k_sage<false, true, false><<<sageBlocks, 256, SMEM_BYTES>>>(h1, wl1, nullptr, bl1, nullptr,
                                                                wl2, bl2, out);
}

// round 15
// speedup vs baseline: 1.7342x; 1.0017x over previous
#include <cuda_runtime.h>
#include <cuda_fp16.h>
#include <cstdint>

#define NN 50000
#define EE 800000
#define F  128
#define FF (F * F)
#define SCAN_BLK 1024
#define SCAN_TILES ((NN + SCAN_BLK - 1) / SCAN_BLK)   // 49

// HMMA smem layout (halves, padded rows: 272 B -> conflict-free ldmatrix)
#define ROWB 272
#define OFF_WH 0
#define OFF_WL (128 * ROWB)
#define OFF_AH (2 * 128 * ROWB)
#define OFF_AL (2 * 128 * ROWB + 64 * ROWB)
#define SMEM_BYTES (2 * 128 * ROWB + 2 * 64 * ROWB)  // 104448

// ================= scratch =================
__device__ int    g_cnt[NN];
__device__ int    g_fill[NN];
__device__ int    g_incl[NN];
__device__ int    g_tsum[SCAN_TILES];
__device__ int    g_toff[SCAN_TILES];
__device__ int    g_rowptr[NN + 1];
__device__ int2   g_edge[EE];            // (src, ew-bits)
__device__ __half g_hh[(size_t)NN * F];  // h hi (in-place per layer)
__device__ __half g_hl[(size_t)NN * F];  // h lo
__device__ __half g_nh[(size_t)NN * F];  // neigh hi
__device__ __half g_nl[(size_t)NN * F];  // neigh lo
__device__ __half g_wspH[7 * FF];        // pre-split weights hi
__device__ __half g_wspL[7 * FF];        // pre-split weights lo

// ================= split helpers =================
__device__ __forceinline__ void split_h(float x, __half& h, __half& l) {
    h = __float2half_rn(x);
    l = __float2half_rn(x - __half2float(h));
}
__device__ __forceinline__ void split4(const float4& v, uint2& ph, uint2& pl) {
    __half h0, h1, h2, h3, l0, l1, l2, l3;
    split_h(v.x, h0, l0); split_h(v.y, h1, l1);
    split_h(v.z, h2, l2); split_h(v.w, h3, l3);
    __half2 a = __halves2half2(h0, h1), b = __halves2half2(h2, h3);
    __half2 c = __halves2half2(l0, l1), d = __halves2half2(l2, l3);
    ph = make_uint2(*reinterpret_cast<uint32_t*>(&a), *reinterpret_cast<uint32_t*>(&b));
    pl = make_uint2(*reinterpret_cast<uint32_t*>(&c), *reinterpret_cast<uint32_t*>(&d));
}

// ================= weight pre-split (once per launch) =================
__global__ void k_wsplit(const float* w0, const float* w1, const float* w2,
                         const float* w3, const float* w4, const float* w5,
                         const float* w6) {
    int i = blockIdx.x * blockDim.x + threadIdx.x;   // 7*FF/4 tasks
    if (i >= 7 * FF / 4) return;
    int m = i / (FF / 4);
    int e = i - m * (FF / 4);
    const float* W = m == 0 ? w0 : m == 1 ? w1 : m == 2 ? w2 :
                     m == 3 ? w3 : m == 4 ? w4 : m == 5 ? w5 : w6;
    float4 v = reinterpret_cast<const float4*>(W)[e];
    uint2 ph, pl;
    split4(v, ph, pl);
    reinterpret_cast<uint2*>(g_wspH)[i] = ph;
    reinterpret_cast<uint2*>(g_wspL)[i] = pl;
}

// ================= input convert (fp32 -> hi/lo halves) =================
__global__ void k_cvt(const float* __restrict__ in) {
    int i = blockIdx.x * blockDim.x + threadIdx.x;   // NN*F/4 tasks
    if (i >= NN * F / 4) return;
    float4 v = reinterpret_cast<const float4*>(in)[i];
    uint2 ph, pl;
    split4(v, ph, pl);
    reinterpret_cast<uint2*>(g_hh)[i] = ph;
    reinterpret_cast<uint2*>(g_hl)[i] = pl;
}

// ================= CSR build =================
__global__ void k_zero() {
    int i = blockIdx.x * blockDim.x + threadIdx.x;
    if (i < NN) { g_cnt[i] = 0; g_fill[i] = 0; }
}
__global__ void k_hist(const int* __restrict__ dst) {
    int e = blockIdx.x * blockDim.x + threadIdx.x;
    if (e < EE) atomicAdd(&g_cnt[dst[e]], 1);
}
__global__ void k_scan1() {
    __shared__ int wsum[32];
    const int tid = threadIdx.x, lane = tid & 31, wid = tid >> 5;
    int idx = blockIdx.x * SCAN_BLK + tid;
    int x = (idx < NN) ? g_cnt[idx] : 0;
#pragma unroll
    for (int off = 1; off < 32; off <<= 1) {
        int y = __shfl_up_sync(0xffffffffu, x, off);
        if (lane >= off) x += y;
    }
    if (lane == 31) wsum[wid] = x;
    __syncthreads();
    if (wid == 0) {
        int s = wsum[lane];
#pragma unroll
        for (int off = 1; off < 32; off <<= 1) {
            int y = __shfl_up_sync(0xffffffffu, s, off);
            if (lane >= off) s += y;
        }
        wsum[lane] = s;
    }
    __syncthreads();
    int incl = x + (wid ? wsum[wid - 1] : 0);
    if (idx < NN) g_incl[idx] = incl;
    if (tid == SCAN_BLK - 1) g_tsum[blockIdx.x] = incl;
}
__global__ void k_scan2() {
    __shared__ int sh[SCAN_TILES];
    const int tid = threadIdx.x;
    if (tid < SCAN_TILES) sh[tid] = g_tsum[tid];
    __syncthreads();
    if (tid == 0) {
        int run = 0;
        for (int i = 0; i < SCAN_TILES; i++) { int v = sh[i]; sh[i] = run; run += v; }
        g_rowptr[NN] = run;
    }
    __syncthreads();
    if (tid < SCAN_TILES) g_toff[tid] = sh[tid];
}
__global__ void k_scan3() {
    int i = blockIdx.x * blockDim.x + threadIdx.x;
    if (i < NN) g_rowptr[i] = g_toff[i / SCAN_BLK] + g_incl[i] - g_cnt[i];
}
__global__ void k_scatter(const int* __restrict__ src, const int* __restrict__ dst,
                          const float* __restrict__ ew) {
    int e = blockIdx.x * blockDim.x + threadIdx.x;
    if (e < EE) {
        int d = dst[e];
        int p = g_rowptr[d] + atomicAdd(&g_fill[d], 1);
        g_edge[p] = make_int2(src[e], __float_as_int(ew[e]));
    }
}

// ================= aggregation: warp/node, lane halves, unroll-4 ============
// Output: hi/lo split of the mean into g_nh/g_nl (no fp32 buffer).
__device__ __forceinline__ void acc_edge(float acc[8], int node, int fl, float wt) {
    const uint4 hv = *reinterpret_cast<const uint4*>(g_hh + (size_t)node * F + fl * 8);
    const __half2* hp = reinterpret_cast<const __half2*>(&hv);
#pragma unroll
    for (int q = 0; q < 4; q++) {
        float2 p = __half22float2(hp[q]);
        acc[2 * q + 0] += wt * p.x;
        acc[2 * q + 1] += wt * p.y;
    }
}

__global__ void k_agg() {
    int v    = (blockIdx.x * blockDim.x + threadIdx.x) >> 5;
    int lane = threadIdx.x & 31;
    if (v >= NN) return;
    const int half = lane >> 4;
    const int fl   = lane & 15;

    int s0 = g_rowptr[v], s1 = g_rowptr[v + 1];
    int deg = s1 - s0;

    float acc[8];
#pragma unroll
    for (int q = 0; q < 8; q++) acc[q] = 0.f;

    int e = s0 + half;
    for (; e + 6 < s1; e += 8) {
        int2 ea = g_edge[e],     eb = g_edge[e + 2];
        int2 ec = g_edge[e + 4], ed = g_edge[e + 6];
        acc_edge(acc, ea.x, fl, __int_as_float(ea.y));
        acc_edge(acc, eb.x, fl, __int_as_float(eb.y));
        acc_edge(acc, ec.x, fl, __int_as_float(ec.y));
        acc_edge(acc, ed.x, fl, __int_as_float(ed.y));
    }
    for (; e < s1; e += 2) {
        int2 ea = g_edge[e];
        acc_edge(acc, ea.x, fl, __int_as_float(ea.y));
    }

#pragma unroll
    for (int q = 0; q < 8; q++)
        acc[q] += __shfl_xor_sync(0xffffffffu, acc[q], 16);

    float invd = 1.0f / (float)(deg > 1 ? deg : 1);
    if (half == 0) {
        float4 v0, v1;
        v0.x = acc[0] * invd; v0.y = acc[1] * invd;
        v0.z = acc[2] * invd; v0.w = acc[3] * invd;
        v1.x = acc[4] * invd; v1.y = acc[5] * invd;
        v1.z = acc[6] * invd; v1.w = acc[7] * invd;
        uint2 ph0, pl0, ph1, pl1;
        split4(v0, ph0, pl0);
        split4(v1, ph1, pl1);
        size_t off = (size_t)v * F + fl * 8;
        *reinterpret_cast<uint4*>(g_nh + off) = make_uint4(ph0.x, ph0.y, ph1.x, ph1.y);
        *reinterpret_cast<uint4*>(g_nl + off) = make_uint4(pl0.x, pl0.y, pl1.x, pl1.y);
    }
}

// ================= HMMA helpers =================
__device__ __forceinline__ uint32_t cvta_sm(const void* p) {
    uint32_t a;
    asm("{ .reg .u64 t; cvta.to.shared.u64 t, %1; cvt.u32.u64 %0, t; }" : "=r"(a) : "l"(p));
    return a;
}
__device__ __forceinline__ void ldsm4(uint32_t* r, uint32_t addr) {
    asm volatile("ldmatrix.sync.aligned.m8n8.x4.shared.b16 {%0,%1,%2,%3}, [%4];"
        : "=r"(r[0]), "=r"(r[1]), "=r"(r[2]), "=r"(r[3]) : "r"(addr));
}
__device__ __forceinline__ void ldsm4t(uint32_t* r, uint32_t addr) {
    asm volatile("ldmatrix.sync.aligned.m8n8.x4.trans.shared.b16 {%0,%1,%2,%3}, [%4];"
        : "=r"(r[0]), "=r"(r[1]), "=r"(r[2]), "=r"(r[3]) : "r"(addr));
}
__device__ __forceinline__ void mma16816(float* d, const uint32_t* a, const uint32_t* b) {
    asm volatile("mma.sync.aligned.m16n8k16.row.col.f32.f16.f16.f32 "
        "{%0,%1,%2,%3}, {%4,%5,%6,%7}, {%8,%9}, {%0,%1,%2,%3};"
        : "+f"(d[0]), "+f"(d[1]), "+f"(d[2]), "+f"(d[3])
        : "r"(a[0]), "r"(a[1]), "r"(a[2]), "r"(a[3]), "r"(b[0]), "r"(b[1]));
}

// ================= fused SAGE GEMM (split HMMA, pure-copy staging) ==========
// 256 threads / 8 warps; tile 64 nodes x 128 feats; 3-term Markidis split.
// A sources: self pass = g_hh/g_hl (in-place update is safe: a block reads only
// its own rows, then overwrites them); neigh pass = g_nh/g_nl.
template <bool HN, bool DOT>
__global__ void __launch_bounds__(256, 2)
k_sage(const __half* __restrict__ wsH, const __half* __restrict__ wsL,
       const __half* __restrict__ wnH, const __half* __restrict__ wnL,
       const float* __restrict__ b,
       const float* __restrict__ w2, const float* __restrict__ b2,
       float* __restrict__ outv) {
    extern __shared__ char smc[];
    const uint32_t sbase = cvta_sm(smc);

    const int tid  = threadIdx.x;
    const int lane = tid & 31;
    const int wid  = tid >> 5;
    const int wm   = wid & 3;
    const int wn2  = wid >> 2;
    const int nodeBase = blockIdx.x * 64;

    float d[8][4];
#pragma unroll
    for (int nf = 0; nf < 8; nf++)
#pragma unroll
        for (int q = 0; q < 4; q++) d[nf][q] = 0.f;

    const int lr = lane & 15, lh = lane >> 4;
    const uint32_t aH = sbase + OFF_AH + (16 * wm + lr) * ROWB + lh * 16;
    const uint32_t aL = sbase + OFF_AL + (16 * wm + lr) * ROWB + lh * 16;
    const uint32_t bH = sbase + OFF_WH + lr * ROWB + (wn2 * 64 + lh * 8) * 2;
    const uint32_t bL = sbase + OFF_WL + lr * ROWB + (wn2 * 64 + lh * 8) * 2;

    for (int pass = 0; pass < (HN ? 2 : 1); pass++) {
        const __half* Wh = (pass == 0) ? wsH : wnH;
        const __half* Wl = (pass == 0) ? wsL : wnL;
        const __half* Ah = (pass == 0) ? g_hh : g_nh;
        const __half* Al = (pass == 0) ? g_hl : g_nl;
        if (pass) __syncthreads();

        // weights: pure uint4 copies (pre-split)
        for (int t = tid; t < 128 * 16; t += 256) {
            int k = t >> 4, u = t & 15;
            *reinterpret_cast<uint4*>(smc + OFF_WH + k * ROWB + u * 16) =
                reinterpret_cast<const uint4*>(Wh + k * F)[u];
            *reinterpret_cast<uint4*>(smc + OFF_WL + k * ROWB + u * 16) =
                reinterpret_cast<const uint4*>(Wl + k * F)[u];
        }
        // node tile: pure uint4 copies
        for (int t = tid; t < 64 * 16; t += 256) {
            int n = t >> 4, u = t & 15;
            int v = nodeBase + n;
            uint4 hv = make_uint4(0, 0, 0, 0), lv = make_uint4(0, 0, 0, 0);
            if (v < NN) {
                hv = reinterpret_cast<const uint4*>(Ah + (size_t)v * F)[u];
                lv = reinterpret_cast<const uint4*>(Al + (size_t)v * F)[u];
            }
            *reinterpret_cast<uint4*>(smc + OFF_AH + n * ROWB + u * 16) = hv;
            *reinterpret_cast<uint4*>(smc + OFF_AL + n * ROWB + u * 16) = lv;
        }
        __syncthreads();

#pragma unroll
        for (int kt = 0; kt < 8; kt++) {
            uint32_t ah[4], al[4];
            ldsm4(ah, aH + kt * 32);
            ldsm4(al, aL + kt * 32);
            uint32_t bh[16], bl[16];
#pragma unroll
            for (int g = 0; g < 4; g++) {
                ldsm4t(bh + 4 * g, bH + kt * (16 * ROWB) + g * 32);
                ldsm4t(bl + 4 * g, bL + kt * (16 * ROWB) + g * 32);
            }
#pragma unroll
            for (int nf = 0; nf < 8; nf++) {
                mma16816(d[nf], ah, bh + 2 * nf);
                mma16816(d[nf], ah, bl + 2 * nf);
                mma16816(d[nf], al, bh + 2 * nf);
            }
        }
    }

    // ---- epilogue ----
    const int r0 = lane >> 2;
    const int c0 = (lane & 3) * 2;
    const int vA = nodeBase + 16 * wm + r0;
    const int vB = vA + 8;

    if (!DOT) {
#pragma unroll
        for (int nf = 0; nf < 8; nf++) {
            int col = wn2 * 64 + nf * 8 + c0;
            float2 bb = *reinterpret_cast<const float2*>(b + col);
            float o0 = fmaxf(d[nf][0] + bb.x, 0.f);
            float o1 = fmaxf(d[nf][1] + bb.y, 0.f);
            float o2 = fmaxf(d[nf][2] + bb.x, 0.f);
            float o3 = fmaxf(d[nf][3] + bb.y, 0.f);
            __half h0, h1, h2, h3, l0, l1, l2, l3;
            split_h(o0, h0, l0); split_h(o1, h1, l1);
            split_h(o2, h2, l2); split_h(o3, h3, l3);
            if (vA < NN) {
                *reinterpret_cast<__half2*>(g_hh + (size_t)vA * F + col) = __halves2half2(h0, h1);
                *reinterpret_cast<__half2*>(g_hl + (size_t)vA * F + col) = __halves2half2(l0, l1);
            }
            if (vB < NN) {
                *reinterpret_cast<__half2*>(g_hh + (size_t)vB * F + col) = __halves2half2(h2, h3);
                *reinterpret_cast<__half2*>(g_hl + (size_t)vB * F + col) = __halves2half2(l2, l3);
            }
        }
    } else {
        __syncthreads();
        float* s_red = reinterpret_cast<float*>(smc);
        if (tid < 64) s_red[tid] = 0.f;
        __syncthreads();
        float pl = 0.f, ph = 0.f;
#pragma unroll
        for (int nf = 0; nf < 8; nf++) {
            int col = wn2 * 64 + nf * 8 + c0;
            float2 bb = *reinterpret_cast<const float2*>(b + col);
            float2 ww = *reinterpret_cast<const float2*>(w2 + col);
            pl += fmaxf(d[nf][0] + bb.x, 0.f) * ww.x + fmaxf(d[nf][1] + bb.y, 0.f) * ww.y;
            ph += fmaxf(d[nf][2] + bb.x, 0.f) * ww.x + fmaxf(d[nf][3] + bb.y, 0.f) * ww.y;
        }
        pl += __shfl_xor_sync(0xffffffffu, pl, 1);
        pl += __shfl_xor_sync(0xffffffffu, pl, 2);
        ph += __shfl_xor_sync(0xffffffffu, ph, 1);
        ph += __shfl_xor_sync(0xffffffffu, ph, 2);
        if ((lane & 3) == 0) {
            atomicAdd(&s_red[16 * wm + r0],     pl);
            atomicAdd(&s_red[16 * wm + r0 + 8], ph);
        }
        __syncthreads();
        if (tid < 64) {
            int v = nodeBase + tid;
            if (v < NN) outv[v] = s_red[tid] + b2[0];
        }
    }
}

// ================= launch =================
extern "C" void kernel_launch(void* const* d_in, const int* in_sizes, int n_in,
                              void* d_out, int out_size) {
    const float* inputs = (const float*)d_in[0];
    const float* ew     = (const float*)d_in[1];
    const int*   src    = (const int*)d_in[2];
    const int*   dst    = (const int*)d_in[3];
    const float* ws1 = (const float*)d_in[4];
    const float* wn1 = (const float*)d_in[5];
    const float* b1  = (const float*)d_in[6];
    const float* ws2 = (const float*)d_in[7];
    const float* wn2 = (const float*)d_in[8];
    const float* b2  = (const float*)d_in[9];
    const float* ws3 = (const float*)d_in[10];
    const float* wn3 = (const float*)d_in[11];
    const float* b3  = (const float*)d_in[12];
    const float* wl1 = (const float*)d_in[13];
    const float* bl1 = (const float*)d_in[14];
    const float* wl2 = (const float*)d_in[15];
    const float* bl2 = (const float*)d_in[16];
    float* out = (float*)d_out;

    __half *wh, *wl;
    cudaGetSymbolAddress((void**)&wh, g_wspH);
    cudaGetSymbolAddress((void**)&wl, g_wspL);

    cudaFuncSetAttribute((const void*)k_sage<true,  false>, cudaFuncAttributeMaxDynamicSharedMemorySize, SMEM_BYTES);
    cudaFuncSetAttribute((const void*)k_sage<false, true>,  cudaFuncAttributeMaxDynamicSharedMemorySize, SMEM_BYTES);

    const int TB = 256;
    const int aggBlocks  = (NN * 32 + TB - 1) / TB;
    const int sageBlocks = (NN + 63) / 64;            // 782

    k_wsplit <<<(7 * FF / 4 + TB - 1) / TB, TB>>>(ws1, wn1, ws2, wn2, ws3, wn3, wl1);
    k_cvt    <<<(NN * F / 4 + TB - 1) / TB, TB>>>(inputs);
    k_zero   <<<(NN + TB - 1) / TB, TB>>>();
    k_hist   <<<(EE + TB - 1) / TB, TB>>>(dst);
    k_scan1  <<<SCAN_TILES, SCAN_BLK>>>();
    k_scan2  <<<1, 64>>>();
    k_scan3  <<<(NN + TB - 1) / TB, TB>>>();
    k_scatter<<<(EE + TB - 1) / TB, TB>>>(src, dst, ew);

    // weight slot order: 0=ws1 1=wn1 2=ws2 3=wn2 4=ws3 5=wn3 6=wl1
    // layer 1
    k_agg<<<aggBlocks, TB>>>();
    k_sage<true, false><<<sageBlocks, 256, SMEM_BYTES>>>(wh + 0 * FF, wl + 0 * FF,
                                                         wh + 1 * FF, wl + 1 * FF,
                                                         b1, nullptr, nullptr, nullptr);
    // layer 2
    k_agg<<<aggBlocks, TB>>>();
    k_sage<true, false><<<sageBlocks, 256, SMEM_BYTES>>>(wh + 2 * FF, wl + 2 * FF,
                                                         wh + 3 * FF, wl + 3 * FF,
                                                         b2, nullptr, nullptr, nullptr);
    // layer 3
    k_agg<<<aggBlocks, TB>>>();
    k_sage<true, false><<<sageBlocks, 256, SMEM_BYTES>>>(wh + 4 * FF, wl + 4 * FF,
                                                         wh + 5 * FF, wl + 5 * FF,
                                                         b3, nullptr, nullptr, nullptr);
    // lin1 + lin2 fused
    k_sage<false, true><<<sageBlocks, 256, SMEM_BYTES>>>(wh + 6 * FF, wl + 6 * FF,
                                                         nullptr, nullptr,
                                                         bl1, wl2, bl2, out);
}

// round 16
// speedup vs baseline: 1.7569x; 1.0131x over previous
#include <cuda_runtime.h>
#include <cuda_fp16.h>
#include <cstdint>

#define NN 50000
#define EE 800000
#define F  128
#define FF (F * F)
#define SCAN_BLK 1024
#define SCAN_TILES ((NN + SCAN_BLK - 1) / SCAN_BLK)   // 49

// HMMA smem layout (halves, padded rows: 272 B -> conflict-free ldmatrix)
// 128-node tile: W (128 k-rows) + A (128 nodes), hi+lo each.
#define ROWB 272
#define OFF_WH 0
#define OFF_WL (128 * ROWB)
#define OFF_AH (2 * 128 * ROWB)
#define OFF_AL (3 * 128 * ROWB)
#define SMEM_BYTES (4 * 128 * ROWB)      // 139264

// ================= scratch =================
__device__ int    g_cnt[NN];
__device__ int    g_fill[NN];
__device__ int    g_incl[NN];
__device__ int    g_tsum[SCAN_TILES];
__device__ int    g_toff[SCAN_TILES];
__device__ int    g_rowptr[NN + 1];
__device__ int2   g_edge[EE];            // (src, ew-bits)
__device__ __half g_hh[(size_t)NN * F];  // h hi (in-place per layer)
__device__ __half g_hl[(size_t)NN * F];  // h lo
__device__ __half g_nh[(size_t)NN * F];  // neigh hi
__device__ __half g_nl[(size_t)NN * F];  // neigh lo
__device__ __half g_wspH[7 * FF];        // pre-split weights hi
__device__ __half g_wspL[7 * FF];        // pre-split weights lo

// ================= split helpers =================
__device__ __forceinline__ void split_h(float x, __half& h, __half& l) {
    h = __float2half_rn(x);
    l = __float2half_rn(x - __half2float(h));
}
__device__ __forceinline__ void split4(const float4& v, uint2& ph, uint2& pl) {
    __half h0, h1, h2, h3, l0, l1, l2, l3;
    split_h(v.x, h0, l0); split_h(v.y, h1, l1);
    split_h(v.z, h2, l2); split_h(v.w, h3, l3);
    __half2 a = __halves2half2(h0, h1), b = __halves2half2(h2, h3);
    __half2 c = __halves2half2(l0, l1), d = __halves2half2(l2, l3);
    ph = make_uint2(*reinterpret_cast<uint32_t*>(&a), *reinterpret_cast<uint32_t*>(&b));
    pl = make_uint2(*reinterpret_cast<uint32_t*>(&c), *reinterpret_cast<uint32_t*>(&d));
}

// ================= weight pre-split (once per launch) =================
__global__ void k_wsplit(const float* w0, const float* w1, const float* w2,
                         const float* w3, const float* w4, const float* w5,
                         const float* w6) {
    int i = blockIdx.x * blockDim.x + threadIdx.x;   // 7*FF/4 tasks
    if (i >= 7 * FF / 4) return;
    int m = i / (FF / 4);
    int e = i - m * (FF / 4);
    const float* W = m == 0 ? w0 : m == 1 ? w1 : m == 2 ? w2 :
                     m == 3 ? w3 : m == 4 ? w4 : m == 5 ? w5 : w6;
    float4 v = reinterpret_cast<const float4*>(W)[e];
    uint2 ph, pl;
    split4(v, ph, pl);
    reinterpret_cast<uint2*>(g_wspH)[i] = ph;
    reinterpret_cast<uint2*>(g_wspL)[i] = pl;
}

// ================= input convert (fp32 -> hi/lo halves) =================
__global__ void k_cvt(const float* __restrict__ in) {
    int i = blockIdx.x * blockDim.x + threadIdx.x;   // NN*F/4 tasks
    if (i >= NN * F / 4) return;
    float4 v = reinterpret_cast<const float4*>(in)[i];
    uint2 ph, pl;
    split4(v, ph, pl);
    reinterpret_cast<uint2*>(g_hh)[i] = ph;
    reinterpret_cast<uint2*>(g_hl)[i] = pl;
}

// ================= CSR build =================
__global__ void k_zero() {
    int i = blockIdx.x * blockDim.x + threadIdx.x;
    if (i < NN) { g_cnt[i] = 0; g_fill[i] = 0; }
}
__global__ void k_hist(const int* __restrict__ dst) {
    int e = blockIdx.x * blockDim.x + threadIdx.x;
    if (e < EE) atomicAdd(&g_cnt[dst[e]], 1);
}
__global__ void k_scan1() {
    __shared__ int wsum[32];
    const int tid = threadIdx.x, lane = tid & 31, wid = tid >> 5;
    int idx = blockIdx.x * SCAN_BLK + tid;
    int x = (idx < NN) ? g_cnt[idx] : 0;
#pragma unroll
    for (int off = 1; off < 32; off <<= 1) {
        int y = __shfl_up_sync(0xffffffffu, x, off);
        if (lane >= off) x += y;
    }
    if (lane == 31) wsum[wid] = x;
    __syncthreads();
    if (wid == 0) {
        int s = wsum[lane];
#pragma unroll
        for (int off = 1; off < 32; off <<= 1) {
            int y = __shfl_up_sync(0xffffffffu, s, off);
            if (lane >= off) s += y;
        }
        wsum[lane] = s;
    }
    __syncthreads();
    int incl = x + (wid ? wsum[wid - 1] : 0);
    if (idx < NN) g_incl[idx] = incl;
    if (tid == SCAN_BLK - 1) g_tsum[blockIdx.x] = incl;
}
__global__ void k_scan2() {
    __shared__ int sh[SCAN_TILES];
    const int tid = threadIdx.x;
    if (tid < SCAN_TILES) sh[tid] = g_tsum[tid];
    __syncthreads();
    if (tid == 0) {
        int run = 0;
        for (int i = 0; i < SCAN_TILES; i++) { int v = sh[i]; sh[i] = run; run += v; }
        g_rowptr[NN] = run;
    }
    __syncthreads();
    if (tid < SCAN_TILES) g_toff[tid] = sh[tid];
}
__global__ void k_scan3() {
    int i = blockIdx.x * blockDim.x + threadIdx.x;
    if (i < NN) g_rowptr[i] = g_toff[i / SCAN_BLK] + g_incl[i] - g_cnt[i];
}
__global__ void k_scatter(const int* __restrict__ src, const int* __restrict__ dst,
                          const float* __restrict__ ew) {
    int e = blockIdx.x * blockDim.x + threadIdx.x;
    if (e < EE) {
        int d = dst[e];
        int p = g_rowptr[d] + atomicAdd(&g_fill[d], 1);
        g_edge[p] = make_int2(src[e], __float_as_int(ew[e]));
    }
}

// ================= aggregation: warp/node, lane halves, unroll-4 ============
__device__ __forceinline__ void acc_edge(float acc[8], int node, int fl, float wt) {
    const uint4 hv = *reinterpret_cast<const uint4*>(g_hh + (size_t)node * F + fl * 8);
    const __half2* hp = reinterpret_cast<const __half2*>(&hv);
#pragma unroll
    for (int q = 0; q < 4; q++) {
        float2 p = __half22float2(hp[q]);
        acc[2 * q + 0] += wt * p.x;
        acc[2 * q + 1] += wt * p.y;
    }
}

__global__ void k_agg() {
    int v    = (blockIdx.x * blockDim.x + threadIdx.x) >> 5;
    int lane = threadIdx.x & 31;
    if (v >= NN) return;
    const int half = lane >> 4;
    const int fl   = lane & 15;

    int s0 = g_rowptr[v], s1 = g_rowptr[v + 1];
    int deg = s1 - s0;

    float acc[8];
#pragma unroll
    for (int q = 0; q < 8; q++) acc[q] = 0.f;

    int e = s0 + half;
    for (; e + 6 < s1; e += 8) {
        int2 ea = g_edge[e],     eb = g_edge[e + 2];
        int2 ec = g_edge[e + 4], ed = g_edge[e + 6];
        acc_edge(acc, ea.x, fl, __int_as_float(ea.y));
        acc_edge(acc, eb.x, fl, __int_as_float(eb.y));
        acc_edge(acc, ec.x, fl, __int_as_float(ec.y));
        acc_edge(acc, ed.x, fl, __int_as_float(ed.y));
    }
    for (; e < s1; e += 2) {
        int2 ea = g_edge[e];
        acc_edge(acc, ea.x, fl, __int_as_float(ea.y));
    }

#pragma unroll
    for (int q = 0; q < 8; q++)
        acc[q] += __shfl_xor_sync(0xffffffffu, acc[q], 16);

    float invd = 1.0f / (float)(deg > 1 ? deg : 1);
    if (half == 0) {
        float4 v0, v1;
        v0.x = acc[0] * invd; v0.y = acc[1] * invd;
        v0.z = acc[2] * invd; v0.w = acc[3] * invd;
        v1.x = acc[4] * invd; v1.y = acc[5] * invd;
        v1.z = acc[6] * invd; v1.w = acc[7] * invd;
        uint2 ph0, pl0, ph1, pl1;
        split4(v0, ph0, pl0);
        split4(v1, ph1, pl1);
        size_t off = (size_t)v * F + fl * 8;
        *reinterpret_cast<uint4*>(g_nh + off) = make_uint4(ph0.x, ph0.y, ph1.x, ph1.y);
        *reinterpret_cast<uint4*>(g_nl + off) = make_uint4(pl0.x, pl0.y, pl1.x, pl1.y);
    }
}

// ================= HMMA helpers =================
__device__ __forceinline__ uint32_t cvta_sm(const void* p) {
    uint32_t a;
    asm("{ .reg .u64 t; cvta.to.shared.u64 t, %1; cvt.u32.u64 %0, t; }" : "=r"(a) : "l"(p));
    return a;
}
__device__ __forceinline__ void ldsm4(uint32_t* r, uint32_t addr) {
    asm volatile("ldmatrix.sync.aligned.m8n8.x4.shared.b16 {%0,%1,%2,%3}, [%4];"
        : "=r"(r[0]), "=r"(r[1]), "=r"(r[2]), "=r"(r[3]) : "r"(addr));
}
__device__ __forceinline__ void ldsm4t(uint32_t* r, uint32_t addr) {
    asm volatile("ldmatrix.sync.aligned.m8n8.x4.trans.shared.b16 {%0,%1,%2,%3}, [%4];"
        : "=r"(r[0]), "=r"(r[1]), "=r"(r[2]), "=r"(r[3]) : "r"(addr));
}
__device__ __forceinline__ void mma16816(float* d, const uint32_t* a, const uint32_t* b) {
    asm volatile("mma.sync.aligned.m16n8k16.row.col.f32.f16.f16.f32 "
        "{%0,%1,%2,%3}, {%4,%5,%6,%7}, {%8,%9}, {%0,%1,%2,%3};"
        : "+f"(d[0]), "+f"(d[1]), "+f"(d[2]), "+f"(d[3])
        : "r"(a[0]), "r"(a[1]), "r"(a[2]), "r"(a[3]), "r"(b[0]), "r"(b[1]));
}

// ================= fused SAGE GEMM (split HMMA, 128-node tile) ==============
// 512 threads / 16 warps; tile 128 nodes x 128 feats; 3-term Markidis split.
// Warp wm=wid&7 -> rows 16*wm..+15; wn2=wid>>3 -> cols 64*wn2..+63.
template <bool HN, bool DOT>
__global__ void __launch_bounds__(512, 1)
k_sage(const __half* __restrict__ wsH, const __half* __restrict__ wsL,
       const __half* __restrict__ wnH, const __half* __restrict__ wnL,
       const float* __restrict__ b,
       const float* __restrict__ w2, const float* __restrict__ b2,
       float* __restrict__ outv) {
    extern __shared__ char smc[];
    const uint32_t sbase = cvta_sm(smc);

    const int tid  = threadIdx.x;
    const int lane = tid & 31;
    const int wid  = tid >> 5;
    const int wm   = wid & 7;
    const int wn2  = wid >> 3;
    const int nodeBase = blockIdx.x * 128;

    float d[8][4];
#pragma unroll
    for (int nf = 0; nf < 8; nf++)
#pragma unroll
        for (int q = 0; q < 4; q++) d[nf][q] = 0.f;

    const int lr = lane & 15, lh = lane >> 4;
    const uint32_t aH = sbase + OFF_AH + (16 * wm + lr) * ROWB + lh * 16;
    const uint32_t aL = sbase + OFF_AL + (16 * wm + lr) * ROWB + lh * 16;
    const uint32_t bH = sbase + OFF_WH + lr * ROWB + (wn2 * 64 + lh * 8) * 2;
    const uint32_t bL = sbase + OFF_WL + lr * ROWB + (wn2 * 64 + lh * 8) * 2;

    for (int pass = 0; pass < (HN ? 2 : 1); pass++) {
        const __half* Wh = (pass == 0) ? wsH : wnH;
        const __half* Wl = (pass == 0) ? wsL : wnL;
        const __half* Ah = (pass == 0) ? g_hh : g_nh;
        const __half* Al = (pass == 0) ? g_hl : g_nl;
        if (pass) __syncthreads();

        // weights: pure uint4 copies (pre-split)
        for (int t = tid; t < 128 * 16; t += 512) {
            int k = t >> 4, u = t & 15;
            *reinterpret_cast<uint4*>(smc + OFF_WH + k * ROWB + u * 16) =
                reinterpret_cast<const uint4*>(Wh + k * F)[u];
            *reinterpret_cast<uint4*>(smc + OFF_WL + k * ROWB + u * 16) =
                reinterpret_cast<const uint4*>(Wl + k * F)[u];
        }
        // node tile: pure uint4 copies
        for (int t = tid; t < 128 * 16; t += 512) {
            int n = t >> 4, u = t & 15;
            int v = nodeBase + n;
            uint4 hv = make_uint4(0, 0, 0, 0), lv = make_uint4(0, 0, 0, 0);
            if (v < NN) {
                hv = reinterpret_cast<const uint4*>(Ah + (size_t)v * F)[u];
                lv = reinterpret_cast<const uint4*>(Al + (size_t)v * F)[u];
            }
            *reinterpret_cast<uint4*>(smc + OFF_AH + n * ROWB + u * 16) = hv;
            *reinterpret_cast<uint4*>(smc + OFF_AL + n * ROWB + u * 16) = lv;
        }
        __syncthreads();

#pragma unroll
        for (int kt = 0; kt < 8; kt++) {
            uint32_t ah[4], al[4];
            ldsm4(ah, aH + kt * 32);
            ldsm4(al, aL + kt * 32);
            uint32_t bh[16], bl[16];
#pragma unroll
            for (int g = 0; g < 4; g++) {
                ldsm4t(bh + 4 * g, bH + kt * (16 * ROWB) + g * 32);
                ldsm4t(bl + 4 * g, bL + kt * (16 * ROWB) + g * 32);
            }
#pragma unroll
            for (int nf = 0; nf < 8; nf++) {
                mma16816(d[nf], ah, bh + 2 * nf);
                mma16816(d[nf], ah, bl + 2 * nf);
                mma16816(d[nf], al, bh + 2 * nf);
            }
        }
    }

    // ---- epilogue ----
    const int r0 = lane >> 2;
    const int c0 = (lane & 3) * 2;
    const int vA = nodeBase + 16 * wm + r0;
    const int vB = vA + 8;

    if (!DOT) {
#pragma unroll
        for (int nf = 0; nf < 8; nf++) {
            int col = wn2 * 64 + nf * 8 + c0;
            float2 bb = *reinterpret_cast<const float2*>(b + col);
            float o0 = fmaxf(d[nf][0] + bb.x, 0.f);
            float o1 = fmaxf(d[nf][1] + bb.y, 0.f);
            float o2 = fmaxf(d[nf][2] + bb.x, 0.f);
            float o3 = fmaxf(d[nf][3] + bb.y, 0.f);
            __half h0, h1, h2, h3, l0, l1, l2, l3;
            split_h(o0, h0, l0); split_h(o1, h1, l1);
            split_h(o2, h2, l2); split_h(o3, h3, l3);
            if (vA < NN) {
                *reinterpret_cast<__half2*>(g_hh + (size_t)vA * F + col) = __halves2half2(h0, h1);
                *reinterpret_cast<__half2*>(g_hl + (size_t)vA * F + col) = __halves2half2(l0, l1);
            }
            if (vB < NN) {
                *reinterpret_cast<__half2*>(g_hh + (size_t)vB * F + col) = __halves2half2(h2, h3);
                *reinterpret_cast<__half2*>(g_hl + (size_t)vB * F + col) = __halves2half2(l2, l3);
            }
        }
    } else {
        __syncthreads();
        float* s_red = reinterpret_cast<float*>(smc);
        if (tid < 128) s_red[tid] = 0.f;
        __syncthreads();
        float pl = 0.f, ph = 0.f;
#pragma unroll
        for (int nf = 0; nf < 8; nf++) {
            int col = wn2 * 64 + nf * 8 + c0;
            float2 bb = *reinterpret_cast<const float2*>(b + col);
            float2 ww = *reinterpret_cast<const float2*>(w2 + col);
            pl += fmaxf(d[nf][0] + bb.x, 0.f) * ww.x + fmaxf(d[nf][1] + bb.y, 0.f) * ww.y;
            ph += fmaxf(d[nf][2] + bb.x, 0.f) * ww.x + fmaxf(d[nf][3] + bb.y, 0.f) * ww.y;
        }
        pl += __shfl_xor_sync(0xffffffffu, pl, 1);
        pl += __shfl_xor_sync(0xffffffffu, pl, 2);
        ph += __shfl_xor_sync(0xffffffffu, ph, 1);
        ph += __shfl_xor_sync(0xffffffffu, ph, 2);
        if ((lane & 3) == 0) {
            atomicAdd(&s_red[16 * wm + r0],     pl);
            atomicAdd(&s_red[16 * wm + r0 + 8], ph);
        }
        __syncthreads();
        if (tid < 128) {
            int v = nodeBase + tid;
            if (v < NN) outv[v] = s_red[tid] + b2[0];
        }
    }
}

// ================= launch =================
extern "C" void kernel_launch(void* const* d_in, const int* in_sizes, int n_in,
                              void* d_out, int out_size) {
    const float* inputs = (const float*)d_in[0];
    const float* ew     = (const float*)d_in[1];
    const int*   src    = (const int*)d_in[2];
    const int*   dst    = (const int*)d_in[3];
    const float* ws1 = (const float*)d_in[4];
    const float* wn1 = (const float*)d_in[5];
    const float* b1  = (const float*)d_in[6];
    const float* ws2 = (const float*)d_in[7];
    const float* wn2 = (const float*)d_in[8];
    const float* b2  = (const float*)d_in[9];
    const float* ws3 = (const float*)d_in[10];
    const float* wn3 = (const float*)d_in[11];
    const float* b3  = (const float*)d_in[12];
    const float* wl1 = (const float*)d_in[13];
    const float* bl1 = (const float*)d_in[14];
    const float* wl2 = (const float*)d_in[15];
    const float* bl2 = (const float*)d_in[16];
    float* out = (float*)d_out;

    __half *wh, *wl;
    cudaGetSymbolAddress((void**)&wh, g_wspH);
    cudaGetSymbolAddress((void**)&wl, g_wspL);

    static bool inited = false;
    static cudaStream_t s2;
    static cudaEvent_t ev0, ev1;
    if (!inited) {
        cudaFuncSetAttribute((const void*)k_sage<true,  false>, cudaFuncAttributeMaxDynamicSharedMemorySize, SMEM_BYTES);
        cudaFuncSetAttribute((const void*)k_sage<false, true>,  cudaFuncAttributeMaxDynamicSharedMemorySize, SMEM_BYTES);
        cudaStreamCreateWithFlags(&s2, cudaStreamNonBlocking);
        cudaEventCreateWithFlags(&ev0, cudaEventDisableTiming);
        cudaEventCreateWithFlags(&ev1, cudaEventDisableTiming);
        inited = true;
    }

    const cudaStream_t m = 0;
    const int TB = 256;
    const int aggBlocks  = (NN * 32 + TB - 1) / TB;
    const int sageBlocks = (NN + 127) / 128;          // 391

    // fork: s2 builds CSR while m pre-splits weights + converts inputs
    cudaEventRecord(ev0, m);
    cudaStreamWaitEvent(s2, ev0, 0);
    k_zero   <<<(NN + TB - 1) / TB, TB, 0, s2>>>();
    k_hist   <<<(EE + TB - 1) / TB, TB, 0, s2>>>(dst);
    k_scan1  <<<SCAN_TILES, SCAN_BLK, 0, s2>>>();
    k_scan2  <<<1, 64, 0, s2>>>();
    k_scan3  <<<(NN + TB - 1) / TB, TB, 0, s2>>>();
    k_scatter<<<(EE + TB - 1) / TB, TB, 0, s2>>>(src, dst, ew);
    k_wsplit <<<(7 * FF / 4 + TB - 1) / TB, TB, 0, m>>>(ws1, wn1, ws2, wn2, ws3, wn3, wl1);
    k_cvt    <<<(NN * F / 4 + TB - 1) / TB, TB, 0, m>>>(inputs);
    cudaEventRecord(ev1, s2);
    cudaStreamWaitEvent(m, ev1, 0);

    // weight slot order: 0=ws1 1=wn1 2=ws2 3=wn2 4=ws3 5=wn3 6=wl1
    // layer 1
    k_agg<<<aggBlocks, TB, 0, m>>>();
    k_sage<true, false><<<sageBlocks, 512, SMEM_BYTES, m>>>(wh + 0 * FF, wl + 0 * FF,
                                                            wh + 1 * FF, wl + 1 * FF,
                                                            b1, nullptr, nullptr, nullptr);
    // layer 2
    k_agg<<<aggBlocks, TB, 0, m>>>();
    k_sage<true, false><<<sageBlocks, 512, SMEM_BYTES, m>>>(wh + 2 * FF, wl + 2 * FF,
                                                            wh + 3 * FF, wl + 3 * FF,
                                                            b2, nullptr, nullptr, nullptr);
    // layer 3
    k_agg<<<aggBlocks, TB, 0, m>>>();
    k_sage<true, false><<<sageBlocks, 512, SMEM_BYTES, m>>>(wh + 4 * FF, wl + 4 * FF,
                                                            wh + 5 * FF, wl + 5 * FF,
                                                            b3, nullptr, nullptr, nullptr);
    // lin1 + lin2 fused
    k_sage<false, true><<<sageBlocks, 512, SMEM_BYTES, m>>>(wh + 6 * FF, wl + 6 * FF,
                                                            nullptr, nullptr,
                                                            bl1, wl2, bl2, out);
}

// round 17
// speedup vs baseline: 1.8333x; 1.0435x over previous
#include <cuda_runtime.h>
#include <cuda_fp16.h>
#include <cstdint>

#define NN 50000
#define EE 800000
#define F  128
#define FF (F * F)
#define SCAN_BLK 1024
#define SCAN_TILES ((NN + SCAN_BLK - 1) / SCAN_BLK)   // 49

// HMMA smem layout (halves, padded rows: 272 B -> conflict-free ldmatrix)
#define ROWB 272
#define OFF_WH 0
#define OFF_WL (128 * ROWB)
#define OFF_AH (2 * 128 * ROWB)
#define OFF_AL (3 * 128 * ROWB)
#define SMEM_BYTES (4 * 128 * ROWB)      // 139264

// ================= scratch =================
__device__ int    g_cnt[NN];
__device__ int    g_fill[NN];
__device__ int    g_incl[NN];
__device__ int    g_tsum[SCAN_TILES];
__device__ int    g_toff[SCAN_TILES];
__device__ int    g_rowptr[NN + 1];
__device__ int2   g_edge[EE];
__device__ __half g_hh[(size_t)NN * F];
__device__ __half g_hl[(size_t)NN * F];
__device__ __half g_nh[(size_t)NN * F];
__device__ __half g_nl[(size_t)NN * F];
__device__ __half g_wspH[7 * FF];
__device__ __half g_wspL[7 * FF];

// ================= split helpers =================
__device__ __forceinline__ void split_h(float x, __half& h, __half& l) {
    h = __float2half_rn(x);
    l = __float2half_rn(x - __half2float(h));
}
__device__ __forceinline__ void split4(const float4& v, uint2& ph, uint2& pl) {
    __half h0, h1, h2, h3, l0, l1, l2, l3;
    split_h(v.x, h0, l0); split_h(v.y, h1, l1);
    split_h(v.z, h2, l2); split_h(v.w, h3, l3);
    __half2 a = __halves2half2(h0, h1), b = __halves2half2(h2, h3);
    __half2 c = __halves2half2(l0, l1), d = __halves2half2(l2, l3);
    ph = make_uint2(*reinterpret_cast<uint32_t*>(&a), *reinterpret_cast<uint32_t*>(&b));
    pl = make_uint2(*reinterpret_cast<uint32_t*>(&c), *reinterpret_cast<uint32_t*>(&d));
}

// ================= weight pre-split =================
__global__ void k_wsplit(const float* w0, const float* w1, const float* w2,
                         const float* w3, const float* w4, const float* w5,
                         const float* w6) {
    int i = blockIdx.x * blockDim.x + threadIdx.x;
    if (i >= 7 * FF / 4) return;
    int m = i / (FF / 4);
    int e = i - m * (FF / 4);
    const float* W = m == 0 ? w0 : m == 1 ? w1 : m == 2 ? w2 :
                     m == 3 ? w3 : m == 4 ? w4 : m == 5 ? w5 : w6;
    float4 v = reinterpret_cast<const float4*>(W)[e];
    uint2 ph, pl;
    split4(v, ph, pl);
    reinterpret_cast<uint2*>(g_wspH)[i] = ph;
    reinterpret_cast<uint2*>(g_wspL)[i] = pl;
}

// ================= input convert =================
__global__ void k_cvt(const float* __restrict__ in) {
    int i = blockIdx.x * blockDim.x + threadIdx.x;
    if (i >= NN * F / 4) return;
    float4 v = reinterpret_cast<const float4*>(in)[i];
    uint2 ph, pl;
    split4(v, ph, pl);
    reinterpret_cast<uint2*>(g_hh)[i] = ph;
    reinterpret_cast<uint2*>(g_hl)[i] = pl;
}

// ================= CSR build =================
__global__ void k_zero() {
    int i = blockIdx.x * blockDim.x + threadIdx.x;
    if (i < NN) { g_cnt[i] = 0; g_fill[i] = 0; }
}
__global__ void k_hist(const int* __restrict__ dst) {
    int e = blockIdx.x * blockDim.x + threadIdx.x;
    if (e < EE) atomicAdd(&g_cnt[dst[e]], 1);
}
__global__ void k_scan1() {
    __shared__ int wsum[32];
    const int tid = threadIdx.x, lane = tid & 31, wid = tid >> 5;
    int idx = blockIdx.x * SCAN_BLK + tid;
    int x = (idx < NN) ? g_cnt[idx] : 0;
#pragma unroll
    for (int off = 1; off < 32; off <<= 1) {
        int y = __shfl_up_sync(0xffffffffu, x, off);
        if (lane >= off) x += y;
    }
    if (lane == 31) wsum[wid] = x;
    __syncthreads();
    if (wid == 0) {
        int s = wsum[lane];
#pragma unroll
        for (int off = 1; off < 32; off <<= 1) {
            int y = __shfl_up_sync(0xffffffffu, s, off);
            if (lane >= off) s += y;
        }
        wsum[lane] = s;
    }
    __syncthreads();
    int incl = x + (wid ? wsum[wid - 1] : 0);
    if (idx < NN) g_incl[idx] = incl;
    if (tid == SCAN_BLK - 1) g_tsum[blockIdx.x] = incl;
}
__global__ void k_scan2() {
    __shared__ int sh[SCAN_TILES];
    const int tid = threadIdx.x;
    if (tid < SCAN_TILES) sh[tid] = g_tsum[tid];
    __syncthreads();
    if (tid == 0) {
        int run = 0;
        for (int i = 0; i < SCAN_TILES; i++) { int v = sh[i]; sh[i] = run; run += v; }
        g_rowptr[NN] = run;
    }
    __syncthreads();
    if (tid < SCAN_TILES) g_toff[tid] = sh[tid];
}
__global__ void k_scan3() {
    int i = blockIdx.x * blockDim.x + threadIdx.x;
    if (i < NN) g_rowptr[i] = g_toff[i / SCAN_BLK] + g_incl[i] - g_cnt[i];
}
__global__ void k_scatter(const int* __restrict__ src, const int* __restrict__ dst,
                          const float* __restrict__ ew) {
    int e = blockIdx.x * blockDim.x + threadIdx.x;
    if (e < EE) {
        int d = dst[e];
        int p = g_rowptr[d] + atomicAdd(&g_fill[d], 1);
        g_edge[p] = make_int2(src[e], __float_as_int(ew[e]));
    }
}

// ================= aggregation =================
__device__ __forceinline__ void acc_edge(float acc[8], int node, int fl, float wt) {
    const uint4 hv = *reinterpret_cast<const uint4*>(g_hh + (size_t)node * F + fl * 8);
    const __half2* hp = reinterpret_cast<const __half2*>(&hv);
#pragma unroll
    for (int q = 0; q < 4; q++) {
        float2 p = __half22float2(hp[q]);
        acc[2 * q + 0] += wt * p.x;
        acc[2 * q + 1] += wt * p.y;
    }
}

__global__ void k_agg() {
    int v    = (blockIdx.x * blockDim.x + threadIdx.x) >> 5;
    int lane = threadIdx.x & 31;
    if (v >= NN) return;
    const int half = lane >> 4;
    const int fl   = lane & 15;

    int s0 = g_rowptr[v], s1 = g_rowptr[v + 1];
    int deg = s1 - s0;

    float acc[8];
#pragma unroll
    for (int q = 0; q < 8; q++) acc[q] = 0.f;

    int e = s0 + half;
    for (; e + 6 < s1; e += 8) {
        int2 ea = g_edge[e],     eb = g_edge[e + 2];
        int2 ec = g_edge[e + 4], ed = g_edge[e + 6];
        acc_edge(acc, ea.x, fl, __int_as_float(ea.y));
        acc_edge(acc, eb.x, fl, __int_as_float(eb.y));
        acc_edge(acc, ec.x, fl, __int_as_float(ec.y));
        acc_edge(acc, ed.x, fl, __int_as_float(ed.y));
    }
    for (; e < s1; e += 2) {
        int2 ea = g_edge[e];
        acc_edge(acc, ea.x, fl, __int_as_float(ea.y));
    }

#pragma unroll
    for (int q = 0; q < 8; q++)
        acc[q] += __shfl_xor_sync(0xffffffffu, acc[q], 16);

    float invd = 1.0f / (float)(deg > 1 ? deg : 1);
    if (half == 0) {
        float4 v0, v1;
        v0.x = acc[0] * invd; v0.y = acc[1] * invd;
        v0.z = acc[2] * invd; v0.w = acc[3] * invd;
        v1.x = acc[4] * invd; v1.y = acc[5] * invd;
        v1.z = acc[6] * invd; v1.w = acc[7] * invd;
        uint2 ph0, pl0, ph1, pl1;
        split4(v0, ph0, pl0);
        split4(v1, ph1, pl1);
        size_t off = (size_t)v * F + fl * 8;
        *reinterpret_cast<uint4*>(g_nh + off) = make_uint4(ph0.x, ph0.y, ph1.x, ph1.y);
        *reinterpret_cast<uint4*>(g_nl + off) = make_uint4(pl0.x, pl0.y, pl1.x, pl1.y);
    }
}

// ================= HMMA + cp.async helpers =================
__device__ __forceinline__ uint32_t cvta_sm(const void* p) {
    uint32_t a;
    asm("{ .reg .u64 t; cvta.to.shared.u64 t, %1; cvt.u32.u64 %0, t; }" : "=r"(a) : "l"(p));
    return a;
}
__device__ __forceinline__ void cp16(uint32_t smem, const void* g) {
    asm volatile("cp.async.cg.shared.global [%0], [%1], 16;" :: "r"(smem), "l"(g));
}
__device__ __forceinline__ void cp16z(uint32_t smem, const void* g, int srcsz) {
    asm volatile("cp.async.cg.shared.global [%0], [%1], 16, %2;"
                 :: "r"(smem), "l"(g), "r"(srcsz));
}
#define CP_COMMIT() asm volatile("cp.async.commit_group;" ::: "memory")
#define CP_WAIT(n)  asm volatile("cp.async.wait_group %0;" :: "n"(n) : "memory")

__device__ __forceinline__ void ldsm4(uint32_t* r, uint32_t addr) {
    asm volatile("ldmatrix.sync.aligned.m8n8.x4.shared.b16 {%0,%1,%2,%3}, [%4];"
        : "=r"(r[0]), "=r"(r[1]), "=r"(r[2]), "=r"(r[3]) : "r"(addr));
}
__device__ __forceinline__ void ldsm4t(uint32_t* r, uint32_t addr) {
    asm volatile("ldmatrix.sync.aligned.m8n8.x4.trans.shared.b16 {%0,%1,%2,%3}, [%4];"
        : "=r"(r[0]), "=r"(r[1]), "=r"(r[2]), "=r"(r[3]) : "r"(addr));
}
__device__ __forceinline__ void mma16816(float* d, const uint32_t* a, const uint32_t* b) {
    asm volatile("mma.sync.aligned.m16n8k16.row.col.f32.f16.f16.f32 "
        "{%0,%1,%2,%3}, {%4,%5,%6,%7}, {%8,%9}, {%0,%1,%2,%3};"
        : "+f"(d[0]), "+f"(d[1]), "+f"(d[2]), "+f"(d[3])
        : "r"(a[0]), "r"(a[1]), "r"(a[2]), "r"(a[3]), "r"(b[0]), "r"(b[1]));
}

// ================= fused SAGE GEMM (split HMMA, cp.async pipelined) =========
// 512 threads / 16 warps; 128-node tile; 2 k-chunks per pass double-buffered:
// issue chunk0+chunk1 cp.async groups, mma kt0..3 under chunk1's flight.
template <bool HN, bool DOT>
__global__ void __launch_bounds__(512, 1)
k_sage(const __half* __restrict__ wsH, const __half* __restrict__ wsL,
       const __half* __restrict__ wnH, const __half* __restrict__ wnL,
       const float* __restrict__ b,
       const float* __restrict__ w2, const float* __restrict__ b2,
       float* __restrict__ outv) {
    extern __shared__ char smc[];
    const uint32_t sbase = cvta_sm(smc);

    const int tid  = threadIdx.x;
    const int lane = tid & 31;
    const int wid  = tid >> 5;
    const int wm   = wid & 7;
    const int wn2  = wid >> 3;
    const int nodeBase = blockIdx.x * 128;

    float d[8][4];
#pragma unroll
    for (int nf = 0; nf < 8; nf++)
#pragma unroll
        for (int q = 0; q < 4; q++) d[nf][q] = 0.f;

    const int lr = lane & 15, lh = lane >> 4;
    const uint32_t aH = sbase + OFF_AH + (16 * wm + lr) * ROWB + lh * 16;
    const uint32_t aL = sbase + OFF_AL + (16 * wm + lr) * ROWB + lh * 16;
    const uint32_t bH = sbase + OFF_WH + lr * ROWB + (wn2 * 64 + lh * 8) * 2;
    const uint32_t bL = sbase + OFF_WL + lr * ROWB + (wn2 * 64 + lh * 8) * 2;

    for (int pass = 0; pass < (HN ? 2 : 1); pass++) {
        const __half* Wh = (pass == 0) ? wsH : wnH;
        const __half* Wl = (pass == 0) ? wsL : wnL;
        const __half* Ah = (pass == 0) ? g_hh : g_nh;
        const __half* Al = (pass == 0) ? g_hl : g_nl;
        if (pass) __syncthreads();    // all warps done reading smem of pass 0

        // ---- issue both chunks as cp.async groups ----
#pragma unroll
        for (int c = 0; c < 2; c++) {
            // W chunk: k rows 64c..64c+63, full 256 B rows (WH + WL)
            for (int t = tid; t < 1024; t += 512) {
                int k = c * 64 + (t >> 4), u = t & 15;
                cp16(sbase + OFF_WH + k * ROWB + u * 16, Wh + k * F + u * 8);
                cp16(sbase + OFF_WL + k * ROWB + u * 16, Wl + k * F + u * 8);
            }
            // A chunk: all 128 node rows, bytes 128c..128c+127 (AH + AL)
            for (int t = tid; t < 1024; t += 512) {
                int n = t >> 3, u = c * 8 + (t & 7);
                int v = nodeBase + n;
                if (v < NN) {
                    cp16(sbase + OFF_AH + n * ROWB + u * 16, Ah + (size_t)v * F + u * 8);
                    cp16(sbase + OFF_AL + n * ROWB + u * 16, Al + (size_t)v * F + u * 8);
                } else {
                    cp16z(sbase + OFF_AH + n * ROWB + u * 16, Ah, 0);
                    cp16z(sbase + OFF_AL + n * ROWB + u * 16, Al, 0);
                }
            }
            CP_COMMIT();
        }

        // ---- chunk 0 ready -> mma kt 0..3 (chunk 1 still in flight) ----
        CP_WAIT(1);
        __syncthreads();
#pragma unroll
        for (int kt = 0; kt < 4; kt++) {
            uint32_t ah[4], al[4];
            ldsm4(ah, aH + kt * 32);
            ldsm4(al, aL + kt * 32);
            uint32_t bh[16], bl[16];
#pragma unroll
            for (int g = 0; g < 4; g++) {
                ldsm4t(bh + 4 * g, bH + kt * (16 * ROWB) + g * 32);
                ldsm4t(bl + 4 * g, bL + kt * (16 * ROWB) + g * 32);
            }
#pragma unroll
            for (int nf = 0; nf < 8; nf++) {
                mma16816(d[nf], ah, bh + 2 * nf);
                mma16816(d[nf], ah, bl + 2 * nf);
                mma16816(d[nf], al, bh + 2 * nf);
            }
        }
        // ---- chunk 1 ready -> mma kt 4..7 ----
        CP_WAIT(0);
        __syncthreads();
#pragma unroll
        for (int kt = 4; kt < 8; kt++) {
            uint32_t ah[4], al[4];
            ldsm4(ah, aH + kt * 32);
            ldsm4(al, aL + kt * 32);
            uint32_t bh[16], bl[16];
#pragma unroll
            for (int g = 0; g < 4; g++) {
                ldsm4t(bh + 4 * g, bH + kt * (16 * ROWB) + g * 32);
                ldsm4t(bl + 4 * g, bL + kt * (16 * ROWB) + g * 32);
            }
#pragma unroll
            for (int nf = 0; nf < 8; nf++) {
                mma16816(d[nf], ah, bh + 2 * nf);
                mma16816(d[nf], ah, bl + 2 * nf);
                mma16816(d[nf], al, bh + 2 * nf);
            }
        }
    }

    // ---- epilogue ----
    const int r0 = lane >> 2;
    const int c0 = (lane & 3) * 2;
    const int vA = nodeBase + 16 * wm + r0;
    const int vB = vA + 8;

    if (!DOT) {
#pragma unroll
        for (int nf = 0; nf < 8; nf++) {
            int col = wn2 * 64 + nf * 8 + c0;
            float2 bb = *reinterpret_cast<const float2*>(b + col);
            float o0 = fmaxf(d[nf][0] + bb.x, 0.f);
            float o1 = fmaxf(d[nf][1] + bb.y, 0.f);
            float o2 = fmaxf(d[nf][2] + bb.x, 0.f);
            float o3 = fmaxf(d[nf][3] + bb.y, 0.f);
            __half h0, h1, h2, h3, l0, l1, l2, l3;
            split_h(o0, h0, l0); split_h(o1, h1, l1);
            split_h(o2, h2, l2); split_h(o3, h3, l3);
            if (vA < NN) {
                *reinterpret_cast<__half2*>(g_hh + (size_t)vA * F + col) = __halves2half2(h0, h1);
                *reinterpret_cast<__half2*>(g_hl + (size_t)vA * F + col) = __halves2half2(l0, l1);
            }
            if (vB < NN) {
                *reinterpret_cast<__half2*>(g_hh + (size_t)vB * F + col) = __halves2half2(h2, h3);
                *reinterpret_cast<__half2*>(g_hl + (size_t)vB * F + col) = __halves2half2(l2, l3);
            }
        }
    } else {
        __syncthreads();
        float* s_red = reinterpret_cast<float*>(smc);
        if (tid < 128) s_red[tid] = 0.f;
        __syncthreads();
        float pl = 0.f, ph = 0.f;
#pragma unroll
        for (int nf = 0; nf < 8; nf++) {
            int col = wn2 * 64 + nf * 8 + c0;
            float2 bb = *reinterpret_cast<const float2*>(b + col);
            float2 ww = *reinterpret_cast<const float2*>(w2 + col);
            pl += fmaxf(d[nf][0] + bb.x, 0.f) * ww.x + fmaxf(d[nf][1] + bb.y, 0.f) * ww.y;
            ph += fmaxf(d[nf][2] + bb.x, 0.f) * ww.x + fmaxf(d[nf][3] + bb.y, 0.f) * ww.y;
        }
        pl += __shfl_xor_sync(0xffffffffu, pl, 1);
        pl += __shfl_xor_sync(0xffffffffu, pl, 2);
        ph += __shfl_xor_sync(0xffffffffu, ph, 1);
        ph += __shfl_xor_sync(0xffffffffu, ph, 2);
        if ((lane & 3) == 0) {
            atomicAdd(&s_red[16 * wm + r0],     pl);
            atomicAdd(&s_red[16 * wm + r0 + 8], ph);
        }
        __syncthreads();
        if (tid < 128) {
            int v = nodeBase + tid;
            if (v < NN) outv[v] = s_red[tid] + b2[0];
        }
    }
}

// ================= launch =================
extern "C" void kernel_launch(void* const* d_in, const int* in_sizes, int n_in,
                              void* d_out, int out_size) {
    const float* inputs = (const float*)d_in[0];
    const float* ew     = (const float*)d_in[1];
    const int*   src    = (const int*)d_in[2];
    const int*   dst    = (const int*)d_in[3];
    const float* ws1 = (const float*)d_in[4];
    const float* wn1 = (const float*)d_in[5];
    const float* b1  = (const float*)d_in[6];
    const float* ws2 = (const float*)d_in[7];
    const float* wn2 = (const float*)d_in[8];
    const float* b2  = (const float*)d_in[9];
    const float* ws3 = (const float*)d_in[10];
    const float* wn3 = (const float*)d_in[11];
    const float* b3  = (const float*)d_in[12];
    const float* wl1 = (const float*)d_in[13];
    const float* bl1 = (const float*)d_in[14];
    const float* wl2 = (const float*)d_in[15];
    const float* bl2 = (const float*)d_in[16];
    float* out = (float*)d_out;

    __half *wh, *wl;
    cudaGetSymbolAddress((void**)&wh, g_wspH);
    cudaGetSymbolAddress((void**)&wl, g_wspL);

    static bool inited = false;
    static cudaStream_t s2;
    static cudaEvent_t ev0, ev1;
    if (!inited) {
        cudaFuncSetAttribute((const void*)k_sage<true,  false>, cudaFuncAttributeMaxDynamicSharedMemorySize, SMEM_BYTES);
        cudaFuncSetAttribute((const void*)k_sage<false, true>,  cudaFuncAttributeMaxDynamicSharedMemorySize, SMEM_BYTES);
        cudaStreamCreateWithFlags(&s2, cudaStreamNonBlocking);
        cudaEventCreateWithFlags(&ev0, cudaEventDisableTiming);
        cudaEventCreateWithFlags(&ev1, cudaEventDisableTiming);
        inited = true;
    }

    const cudaStream_t m = 0;
    const int TB = 256;
    const int aggBlocks  = (NN * 32 + TB - 1) / TB;
    const int sageBlocks = (NN + 127) / 128;          // 391

    // fork: s2 builds CSR while m pre-splits weights + converts inputs
    cudaEventRecord(ev0, m);
    cudaStreamWaitEvent(s2, ev0, 0);
    k_zero   <<<(NN + TB - 1) / TB, TB, 0, s2>>>();
    k_hist   <<<(EE + TB - 1) / TB, TB, 0, s2>>>(dst);
    k_scan1  <<<SCAN_TILES, SCAN_BLK, 0, s2>>>();
    k_scan2  <<<1, 64, 0, s2>>>();
    k_scan3  <<<(NN + TB - 1) / TB, TB, 0, s2>>>();
    k_scatter<<<(EE + TB - 1) / TB, TB, 0, s2>>>(src, dst, ew);
    k_wsplit <<<(7 * FF / 4 + TB - 1) / TB, TB, 0, m>>>(ws1, wn1, ws2, wn2, ws3, wn3, wl1);
    k_cvt    <<<(NN * F / 4 + TB - 1) / TB, TB, 0, m>>>(inputs);
    cudaEventRecord(ev1, s2);
    cudaStreamWaitEvent(m, ev1, 0);

    // layer 1
    k_agg<<<aggBlocks, TB, 0, m>>>();
    k_sage<true, false><<<sageBlocks, 512, SMEM_BYTES, m>>>(wh + 0 * FF, wl + 0 * FF,
                                                            wh + 1 * FF, wl + 1 * FF,
                                                            b1, nullptr, nullptr, nullptr);
    // layer 2
    k_agg<<<aggBlocks, TB, 0, m>>>();
    k_sage<true, false><<<sageBlocks, 512, SMEM_BYTES, m>>>(wh + 2 * FF, wl + 2 * FF,
                                                            wh + 3 * FF, wl + 3 * FF,
                                                            b2, nullptr, nullptr, nullptr);
    // layer 3
    k_agg<<<aggBlocks, TB, 0, m>>>();
    k_sage<true, false><<<sageBlocks, 512, SMEM_BYTES, m>>>(wh + 4 * FF, wl + 4 * FF,
                                                            wh + 5 * FF, wl + 5 * FF,
                                                            b3, nullptr, nullptr, nullptr);
    // lin1 + lin2 fused
    k_sage<false, true><<<sageBlocks, 512, SMEM_BYTES, m>>>(wh + 6 * FF, wl + 6 * FF,
                                                            nullptr, nullptr,
                                                            bl1, wl2, bl2, out);
}